// round 2
// baseline (speedup 1.0000x reference)
#include <cuda_runtime.h>
#include <math.h>

#define NN 50000
#define EE 400000
#define RR 4
#define HH 2
#define CC 64
#define HCC 128   // H*C
#define RHC 512   // R*H*C
#define HIDD 64
#define LL 2
#define LN_EPS 1e-5f
#define SLOPE 0.2f

// ---------------- scratch (device globals; no allocations allowed) ----------
__device__ float    g_feat[NN * RHC];   // [n][r*128 + h*64 + c]  per-layer transformed features
__device__ float    g_agg [NN * RHC];   // GAT outputs (post softmax-agg + bias)
__device__ float    g_es  [NN * 8];     // [n][r*2+h] alpha_src per node
__device__ float    g_ed  [NN * 8];
__device__ float    g_eself[NN * 8];    // self-loop logit
__device__ unsigned g_emaxE[NN * 8];    // encoded (monotonic uint) segment max
__device__ float    g_emaxf[NN * 8];
__device__ float    g_den [NN * 8];     // softmax denominator
__device__ float    g_pself[NN * 8];
__device__ float    g_pbuf[EE * 4];     // per-edge exp(e - emax): [e][dir*2 + h]
__device__ float    g_h   [NN * 64];    // hidden state between layers

__device__ __forceinline__ float lrelu(float x) { return x > 0.f ? x : SLOPE * x; }
// monotonic encoding so unsigned atomicMax == float max
__device__ __forceinline__ unsigned encf(float f) {
    unsigned u = __float_as_uint(f);
    return (u & 0x80000000u) ? ~u : (u | 0x80000000u);
}
__device__ __forceinline__ float decf(unsigned u) {
    return __uint_as_float((u & 0x80000000u) ? (u & 0x7fffffffu) : ~u);
}

// ---------------- K1: feat = h @ W[l]  (64 -> 512, i.e. 4 relations x 128) ---
__global__ void k_feat(const float* __restrict__ hin, const float* __restrict__ W)
{
    __shared__ float As[64][64];    // 64 nodes x K=64
    __shared__ float Bs[64][128];   // K=64 x 128 cols (one relation)
    const int tid = threadIdx.x;
    const int r   = blockIdx.y;           // relation = column tile
    const int nb  = blockIdx.x * 64;

    float4* As4 = (float4*)As;
    float4* Bs4 = (float4*)Bs;

    #pragma unroll
    for (int i = 0; i < 4; i++) {         // 64*64 floats = 1024 float4
        int f = tid + i * 256;
        int row = f >> 4, c = f & 15;
        int n = nb + row;
        float4 v = make_float4(0.f, 0.f, 0.f, 0.f);
        if (n < NN) v = ((const float4*)hin)[n * 16 + c];
        As4[f] = v;
    }
    const float4* W4 = (const float4*)(W + r * 64 * 128);
    #pragma unroll
    for (int i = 0; i < 8; i++) {         // 64*128 floats = 2048 float4
        int f = tid + i * 256;
        Bs4[f] = W4[f];
    }
    __syncthreads();

    const int tx = tid & 31, ty = tid >> 5;   // tx: 32 col-groups(x4), ty: 8 node-groups(x8)
    float4 acc[8];
    #pragma unroll
    for (int j = 0; j < 8; j++) acc[j] = make_float4(0.f, 0.f, 0.f, 0.f);

    #pragma unroll
    for (int k = 0; k < 64; k++) {
        float4 b = Bs4[k * 32 + tx];
        #pragma unroll
        for (int j = 0; j < 8; j++) {
            float a = As[ty * 8 + j][k];
            acc[j].x += a * b.x; acc[j].y += a * b.y;
            acc[j].z += a * b.z; acc[j].w += a * b.w;
        }
    }
    #pragma unroll
    for (int j = 0; j < 8; j++) {
        int n = nb + ty * 8 + j;
        if (n < NN) ((float4*)g_feat)[n * 128 + r * 32 + tx] = acc[j];
    }
}

// ---------------- K2: per-(n,r,h) attention scores + self-loop init ---------
__global__ void k_scores(const float* __restrict__ asrc, const float* __restrict__ adst)
{
    int gw = blockIdx.x * 8 + (threadIdx.x >> 5);   // warp id = n*8 + r*2 + h
    if (gw >= NN * 8) return;
    int lane = threadIdx.x & 31;
    int n = gw >> 3, rh = gw & 7;
    // feat as float2: row = 256 f2; offset r*64 + h*32 + lane
    float2 f  = ((const float2*)g_feat)[n * 256 + rh * 32 + lane];
    float2 as = ((const float2*)asrc)[rh * 32 + lane];
    float2 ad = ((const float2*)adst)[rh * 32 + lane];
    float es = f.x * as.x + f.y * as.y;
    float ed = f.x * ad.x + f.y * ad.y;
    #pragma unroll
    for (int o = 16; o; o >>= 1) {
        es += __shfl_xor_sync(0xffffffffu, es, o);
        ed += __shfl_xor_sync(0xffffffffu, ed, o);
    }
    if (lane == 0) {
        g_es[gw] = es;
        g_ed[gw] = ed;
        float e0 = lrelu(es + ed);       // self loop logit
        g_eself[gw] = e0;
        g_emaxE[gw] = encf(e0);          // init segment max with self loop
    }
}

// ---------------- K3: edge segment max (atomicMax on encoded float) ---------
__global__ void k_edge_max(const int* __restrict__ ei, const float* __restrict__ ew)
{
    int e = blockIdx.x * blockDim.x + threadIdx.x;
    if (e >= EE) return;
    int s = ei[e], d = ei[EE + e];
    float w = ew[e];
    if (w == 0.f) return;
    int r0 = (w > 0.f) ? 0 : 2;
    #pragma unroll
    for (int h = 0; h < 2; h++) {
        // out direction: relation r0, src=s dst=d
        float e1 = lrelu(g_es[s * 8 + r0 * 2 + h] + g_ed[d * 8 + r0 * 2 + h]);
        atomicMax(&g_emaxE[d * 8 + r0 * 2 + h], encf(e1));
        // in direction: relation r0+1, src=d dst=s
        float e2 = lrelu(g_es[d * 8 + (r0 + 1) * 2 + h] + g_ed[s * 8 + (r0 + 1) * 2 + h]);
        atomicMax(&g_emaxE[s * 8 + (r0 + 1) * 2 + h], encf(e2));
    }
}

// ---------------- K4: decode max, init denominator with self-loop term ------
__global__ void k_prep()
{
    int i = blockIdx.x * blockDim.x + threadIdx.x;
    if (i >= NN * 8) return;
    float em = decf(g_emaxE[i]);
    g_emaxf[i] = em;
    float p = expf(g_eself[i] - em);
    g_pself[i] = p;
    g_den[i]   = p;
}

// ---------------- K5: edge exp + denominator accumulation -------------------
__global__ void k_edge_sum(const int* __restrict__ ei, const float* __restrict__ ew)
{
    int e = blockIdx.x * blockDim.x + threadIdx.x;
    if (e >= EE) return;
    int s = ei[e], d = ei[EE + e];
    float w = ew[e];
    if (w == 0.f) return;
    int r0 = (w > 0.f) ? 0 : 2;
    #pragma unroll
    for (int h = 0; h < 2; h++) {
        int id = d * 8 + r0 * 2 + h;
        float e1 = lrelu(g_es[s * 8 + r0 * 2 + h] + g_ed[id]);
        float p1 = expf(e1 - g_emaxf[id]);
        g_pbuf[e * 4 + h] = p1;
        atomicAdd(&g_den[id], p1);

        int is = s * 8 + (r0 + 1) * 2 + h;
        float e2 = lrelu(g_es[d * 8 + (r0 + 1) * 2 + h] + g_ed[is]);
        float p2 = expf(e2 - g_emaxf[is]);
        g_pbuf[e * 4 + 2 + h] = p2;
        atomicAdd(&g_den[is], p2);
    }
}

// ---------------- K6: init agg with self-loop contribution + bias -----------
__global__ void k_agg_init(const float* __restrict__ bias)
{
    int wp = blockIdx.x * 8 + (threadIdx.x >> 5);    // wp = n*4 + r
    if (wp >= NN * 4) return;
    int lane = threadIdx.x & 31;
    int n = wp >> 2, r = wp & 3;
    int head = lane >> 4;                            // floats [lane*4, +4) -> head
    int i = n * 8 + r * 2 + head;
    float a = g_pself[i] / g_den[i];
    float4 f = ((const float4*)g_feat)[n * 128 + r * 32 + lane];
    float4 b = ((const float4*)bias)[r * 32 + lane];
    ((float4*)g_agg)[n * 128 + r * 32 + lane] =
        make_float4(f.x * a + b.x, f.y * a + b.y, f.z * a + b.z, f.w * a + b.w);
}

// ---------------- K7: edge aggregation (warp per edge, atomic scatter) ------
__global__ void k_edge_agg(const int* __restrict__ ei, const float* __restrict__ ew)
{
    int e = blockIdx.x * 8 + (threadIdx.x >> 5);
    if (e >= EE) return;
    int lane = threadIdx.x & 31;
    int s = ei[e], d = ei[EE + e];
    float w = ew[e];
    if (w == 0.f) return;
    int r0 = (w > 0.f) ? 0 : 2;
    int head = lane >> 4;

    // out direction: r0, source s -> dest d
    {
        float alpha = g_pbuf[e * 4 + head] / g_den[d * 8 + r0 * 2 + head];
        float4 f = ((const float4*)g_feat)[s * 128 + r0 * 32 + lane];
        float* o = g_agg + d * 512 + r0 * 128 + lane * 4;
        atomicAdd(o + 0, f.x * alpha);
        atomicAdd(o + 1, f.y * alpha);
        atomicAdd(o + 2, f.z * alpha);
        atomicAdd(o + 3, f.w * alpha);
    }
    // in direction: r0+1, source d -> dest s
    {
        int r1 = r0 + 1;
        float alpha = g_pbuf[e * 4 + 2 + head] / g_den[s * 8 + r1 * 2 + head];
        float4 f = ((const float4*)g_feat)[d * 128 + r1 * 32 + lane];
        float* o = g_agg + s * 512 + r1 * 128 + lane * 4;
        atomicAdd(o + 0, f.x * alpha);
        atomicAdd(o + 1, f.y * alpha);
        atomicAdd(o + 2, f.z * alpha);
        atomicAdd(o + 3, f.w * alpha);
    }
}

// ---------------- K8: MLP (tanh) + residual + LayerNorm ---------------------
__global__ void k_mlp(const float* __restrict__ hin,
                      const float* __restrict__ W1, const float* __restrict__ b1,
                      const float* __restrict__ W2, const float* __restrict__ b2,
                      const float* __restrict__ lng, const float* __restrict__ lnb,
                      float* __restrict__ hout)
{
    __shared__ float As[64][64];
    __shared__ float Ws[64][64];
    __shared__ float Zs[64][64];
    const int tid = threadIdx.x;
    const int tx = tid & 15, ty = tid >> 4;     // 16 col-groups(x4), 16 node-groups(x4)
    const int nb = blockIdx.x * 64;
    float4* As4 = (float4*)As;
    float4* Ws4 = (float4*)Ws;
    float4* Zs4 = (float4*)Zs;

    float4 acc[4];
    #pragma unroll
    for (int j = 0; j < 4; j++) acc[j] = make_float4(0.f, 0.f, 0.f, 0.f);

    // z1 = tanh(comb @ W1 + b1), comb = [hin(64) | agg(512)], K = 576 in 9 chunks
    for (int kc = 0; kc < 9; kc++) {
        #pragma unroll
        for (int i = 0; i < 4; i++) {
            int f = tid + i * 256;
            int row = f >> 4, c = f & 15;
            int n = nb + row;
            float4 v = make_float4(0.f, 0.f, 0.f, 0.f);
            if (n < NN) {
                v = (kc == 0) ? ((const float4*)hin)[n * 16 + c]
                              : ((const float4*)g_agg)[n * 128 + (kc - 1) * 16 + c];
            }
            As4[f] = v;
        }
        #pragma unroll
        for (int i = 0; i < 4; i++) {
            int f = tid + i * 256;
            Ws4[f] = ((const float4*)W1)[kc * 1024 + f];   // 64 rows x 16 f4
        }
        __syncthreads();
        #pragma unroll
        for (int k = 0; k < 64; k++) {
            float4 wv = Ws4[k * 16 + tx];
            #pragma unroll
            for (int j = 0; j < 4; j++) {
                float a = As[ty * 4 + j][k];
                acc[j].x += a * wv.x; acc[j].y += a * wv.y;
                acc[j].z += a * wv.z; acc[j].w += a * wv.w;
            }
        }
        __syncthreads();
    }
    float4 bv = ((const float4*)b1)[tx];
    #pragma unroll
    for (int j = 0; j < 4; j++) {
        float4 z;
        z.x = tanhf(acc[j].x + bv.x);
        z.y = tanhf(acc[j].y + bv.y);
        z.z = tanhf(acc[j].z + bv.z);
        z.w = tanhf(acc[j].w + bv.w);
        Zs4[(ty * 4 + j) * 16 + tx] = z;
    }
    #pragma unroll
    for (int i = 0; i < 4; i++) {
        int f = tid + i * 256;
        Ws4[f] = ((const float4*)W2)[f];
    }
    __syncthreads();

    float4 a2[4];
    #pragma unroll
    for (int j = 0; j < 4; j++) a2[j] = make_float4(0.f, 0.f, 0.f, 0.f);
    #pragma unroll
    for (int k = 0; k < 64; k++) {
        float4 wv = Ws4[k * 16 + tx];
        #pragma unroll
        for (int j = 0; j < 4; j++) {
            float a = Zs[ty * 4 + j][k];
            a2[j].x += a * wv.x; a2[j].y += a * wv.y;
            a2[j].z += a * wv.z; a2[j].w += a * wv.w;
        }
    }
    __syncthreads();   // done reading z1 from Zs

    float4 b2v = ((const float4*)b2)[tx];
    #pragma unroll
    for (int j = 0; j < 4; j++) {
        int n = nb + ty * 4 + j;
        float4 res = (n < NN) ? ((const float4*)hin)[n * 16 + tx]
                              : make_float4(0.f, 0.f, 0.f, 0.f);
        float4 z;
        z.x = a2[j].x + b2v.x + res.x;
        z.y = a2[j].y + b2v.y + res.y;
        z.z = a2[j].z + b2v.z + res.z;
        z.w = a2[j].w + b2v.w + res.w;
        Zs4[(ty * 4 + j) * 16 + tx] = z;
    }
    __syncthreads();

    // LayerNorm per row (8 warps x 8 rows)
    int lane = tid & 31, wpid = tid >> 5;
    for (int row = wpid; row < 64; row += 8) {
        float v0 = Zs[row][lane], v1 = Zs[row][lane + 32];
        float s = v0 + v1, q = v0 * v0 + v1 * v1;
        #pragma unroll
        for (int o = 16; o; o >>= 1) {
            s += __shfl_xor_sync(0xffffffffu, s, o);
            q += __shfl_xor_sync(0xffffffffu, q, o);
        }
        float mu = s * (1.f / 64.f);
        float var = q * (1.f / 64.f) - mu * mu;
        float rs = rsqrtf(var + LN_EPS);
        int n = nb + row;
        if (n < NN) {
            hout[n * 64 + lane]      = (v0 - mu) * rs * lng[lane] + lnb[lane];
            hout[n * 64 + lane + 32] = (v1 - mu) * rs * lng[lane + 32] + lnb[lane + 32];
        }
    }
}

// ---------------- launch -----------------------------------------------------
extern "C" void kernel_launch(void* const* d_in, const int* in_sizes, int n_in,
                              void* d_out, int out_size)
{
    const float* x   = (const float*)d_in[0];
    const int*   ei  = (const int*)  d_in[1];
    const float* ew  = (const float*)d_in[2];
    const float* gW  = (const float*)d_in[3];
    const float* gas = (const float*)d_in[4];
    const float* gad = (const float*)d_in[5];
    const float* gb  = (const float*)d_in[6];
    const float* W1  = (const float*)d_in[7];
    const float* b1  = (const float*)d_in[8];
    const float* W2  = (const float*)d_in[9];
    const float* b2  = (const float*)d_in[10];
    const float* lng = (const float*)d_in[11];
    const float* lnb = (const float*)d_in[12];
    float* out = (float*)d_out;

    float* hptr = nullptr;
    cudaGetSymbolAddress((void**)&hptr, g_h);

    const int NT = (NN + 63) / 64;          // 782 node tiles
    const int EB = (EE + 255) / 256;        // 1563 edge blocks
    const int NB8 = (NN * 8 + 255) / 256;   // 1563 node-rel-head blocks

    for (int l = 0; l < LL; l++) {
        const float* hin  = (l == 0) ? x : hptr;
        float*       hout = (l == 0) ? hptr : out;

        k_feat<<<dim3(NT, RR), 256>>>(hin, gW + l * RR * 64 * 128);
        k_scores<<<NN * 8 / 8, 256>>>(gas + l * RR * HH * CC, gad + l * RR * HH * CC);
        k_edge_max<<<EB, 256>>>(ei, ew);
        k_prep<<<NB8, 256>>>();
        k_edge_sum<<<EB, 256>>>(ei, ew);
        k_agg_init<<<NN * 4 / 8, 256>>>(gb + l * RR * HCC);
        k_edge_agg<<<EE / 8, 256>>>(ei, ew);
        k_mlp<<<NT, 256>>>(hin,
                           W1 + l * 576 * 64, b1 + l * 64,
                           W2 + l * 64 * 64,  b2 + l * 64,
                           lng + l * 64, lnb + l * 64, hout);
    }
}

// round 3
// speedup vs baseline: 1.3385x; 1.3385x over previous
#include <cuda_runtime.h>
#include <math.h>

#define NN 50000
#define EE 400000
#define RR 4
#define HH 2
#define CC 64
#define HCC 128   // H*C
#define RHC 512   // R*H*C
#define LL 2
#define LN_EPS 1e-5f
#define SLOPE 0.2f

#define KEYS (NN * RR)          // 200000 (node, relation) segments
#define SCAN_B 1024
#define SCAN_NBLK ((KEYS + SCAN_B - 1) / SCAN_B)   // 196

// ---------------- scratch (device globals; no allocations allowed) ----------
__device__ float g_feat[NN * RHC];   // [n][r*128 + h*64 + c]
__device__ float g_agg [NN * RHC];   // GAT outputs (post softmax-agg + bias)
__device__ float g_es  [NN * 8];     // [n][r*2+h] alpha_src per node
__device__ float g_ed  [NN * 8];
__device__ float g_h   [NN * 64];    // hidden state between layers
// CSR (built once per call; graph identical across layers)
__device__ int   g_cnt[KEYS];
__device__ int   g_off[KEYS];
__device__ int   g_cur[KEYS];
__device__ int   g_bsum[SCAN_NBLK];
__device__ int   g_src[2 * EE];      // adjacency: src node per (dest,rel) entry

__device__ __forceinline__ float lrelu(float x) { return x > 0.f ? x : SLOPE * x; }

// ================= CSR build =================================================
__global__ void k_zero()
{
    int i = blockIdx.x * blockDim.x + threadIdx.x;
    if (i < KEYS) g_cnt[i] = 0;
}

__global__ void k_count(const int* __restrict__ ei, const float* __restrict__ ew)
{
    int e = blockIdx.x * blockDim.x + threadIdx.x;
    if (e >= EE) return;
    int s = ei[e], d = ei[EE + e];
    float w = ew[e];
    if (w == 0.f) return;
    int r0 = (w > 0.f) ? 0 : 2;
    atomicAdd(&g_cnt[d * 4 + r0], 1);        // out direction: dst receives from src
    atomicAdd(&g_cnt[s * 4 + r0 + 1], 1);    // in  direction (reversed)
}

__global__ void k_scan1()
{
    __shared__ int sh[SCAN_B];
    int tid = threadIdx.x;
    int i = blockIdx.x * SCAN_B + tid;
    int v = (i < KEYS) ? g_cnt[i] : 0;
    sh[tid] = v;
    __syncthreads();
    #pragma unroll
    for (int off = 1; off < SCAN_B; off <<= 1) {
        int t = (tid >= off) ? sh[tid - off] : 0;
        __syncthreads();
        sh[tid] += t;
        __syncthreads();
    }
    if (i < KEYS) g_off[i] = sh[tid] - v;        // exclusive within block
    if (tid == SCAN_B - 1) g_bsum[blockIdx.x] = sh[tid];
}

__global__ void k_scan2()
{
    if (threadIdx.x == 0) {
        int run = 0;
        for (int b = 0; b < SCAN_NBLK; b++) {
            int t = g_bsum[b];
            g_bsum[b] = run;
            run += t;
        }
    }
}

__global__ void k_scan3()
{
    int i = blockIdx.x * blockDim.x + threadIdx.x;
    if (i >= KEYS) return;
    int o = g_off[i] + g_bsum[i >> 10];
    g_off[i] = o;
    g_cur[i] = o;
}

__global__ void k_fill(const int* __restrict__ ei, const float* __restrict__ ew)
{
    int e = blockIdx.x * blockDim.x + threadIdx.x;
    if (e >= EE) return;
    int s = ei[e], d = ei[EE + e];
    float w = ew[e];
    if (w == 0.f) return;
    int r0 = (w > 0.f) ? 0 : 2;
    int p1 = atomicAdd(&g_cur[d * 4 + r0], 1);
    g_src[p1] = s;
    int p2 = atomicAdd(&g_cur[s * 4 + r0 + 1], 1);
    g_src[p2] = d;
}

// ---------------- K1: feat = h @ W[l]  (64 -> 512 = 4 relations x 128) ------
__global__ void k_feat(const float* __restrict__ hin, const float* __restrict__ W)
{
    __shared__ float As[64][64];
    __shared__ float Bs[64][128];
    const int tid = threadIdx.x;
    const int r   = blockIdx.y;
    const int nb  = blockIdx.x * 64;

    float4* As4 = (float4*)As;
    float4* Bs4 = (float4*)Bs;

    #pragma unroll
    for (int i = 0; i < 4; i++) {
        int f = tid + i * 256;
        int row = f >> 4, c = f & 15;
        int n = nb + row;
        float4 v = make_float4(0.f, 0.f, 0.f, 0.f);
        if (n < NN) v = ((const float4*)hin)[n * 16 + c];
        As4[f] = v;
    }
    const float4* W4 = (const float4*)(W + r * 64 * 128);
    #pragma unroll
    for (int i = 0; i < 8; i++) {
        int f = tid + i * 256;
        Bs4[f] = W4[f];
    }
    __syncthreads();

    const int tx = tid & 31, ty = tid >> 5;
    float4 acc[8];
    #pragma unroll
    for (int j = 0; j < 8; j++) acc[j] = make_float4(0.f, 0.f, 0.f, 0.f);

    #pragma unroll
    for (int k = 0; k < 64; k++) {
        float4 b = Bs4[k * 32 + tx];
        #pragma unroll
        for (int j = 0; j < 8; j++) {
            float a = As[ty * 8 + j][k];
            acc[j].x += a * b.x; acc[j].y += a * b.y;
            acc[j].z += a * b.z; acc[j].w += a * b.w;
        }
    }
    #pragma unroll
    for (int j = 0; j < 8; j++) {
        int n = nb + ty * 8 + j;
        if (n < NN) ((float4*)g_feat)[n * 128 + r * 32 + tx] = acc[j];
    }
}

// ---------------- K2: per-(n,r,h) attention dot products --------------------
__global__ void k_scores(const float* __restrict__ asrc, const float* __restrict__ adst)
{
    int gw = blockIdx.x * 8 + (threadIdx.x >> 5);   // warp = n*8 + r*2 + h
    if (gw >= NN * 8) return;
    int lane = threadIdx.x & 31;
    int n = gw >> 3, rh = gw & 7;
    float2 f  = ((const float2*)g_feat)[n * 256 + rh * 32 + lane];
    float2 as = ((const float2*)asrc)[rh * 32 + lane];
    float2 ad = ((const float2*)adst)[rh * 32 + lane];
    float es = f.x * as.x + f.y * as.y;
    float ed = f.x * ad.x + f.y * ad.y;
    #pragma unroll
    for (int o = 16; o; o >>= 1) {
        es += __shfl_xor_sync(0xffffffffu, es, o);
        ed += __shfl_xor_sync(0xffffffffu, ed, o);
    }
    if (lane == 0) {
        g_es[gw] = es;
        g_ed[gw] = ed;
    }
}

// ---------------- K3: fused GAT softmax + aggregation (no atomics) ----------
// One warp per (node, relation). Two passes over the CSR incoming-edge list:
// pass 1 = segment max; pass 2 = unnormalized exp-weighted aggregation.
__global__ void k_gat(const float* __restrict__ bias)
{
    const unsigned FULL = 0xffffffffu;
    int key = blockIdx.x * 8 + (threadIdx.x >> 5);
    if (key >= KEYS) return;
    int lane = threadIdx.x & 31;
    int n = key >> 2, r = key & 3;

    int beg = g_off[key];
    int num = g_cnt[key];

    float2 edv = ((const float2*)g_ed)[n * 4 + r];   // ed[n, r, h0/h1]
    float2 esn = ((const float2*)g_es)[n * 4 + r];   // es[n, ...] (self loop)
    float self0 = lrelu(esn.x + edv.x);
    float self1 = lrelu(esn.y + edv.y);

    // ---- pass 1: max over incoming edges (init = self-loop logit) ----
    float m0 = self0, m1 = self1;
    for (int i = lane; i < num; i += 32) {
        int s = g_src[beg + i];
        float2 e2 = ((const float2*)g_es)[s * 4 + r];
        m0 = fmaxf(m0, lrelu(e2.x + edv.x));
        m1 = fmaxf(m1, lrelu(e2.y + edv.y));
    }
    #pragma unroll
    for (int o = 16; o; o >>= 1) {
        m0 = fmaxf(m0, __shfl_xor_sync(FULL, m0, o));
        m1 = fmaxf(m1, __shfl_xor_sync(FULL, m1, o));
    }

    // ---- pass 2: den += p, acc += p * h_src  (normalize at the end) ----
    float den0 = 0.f, den1 = 0.f;
    float4 acc = make_float4(0.f, 0.f, 0.f, 0.f);
    const float4* feat4 = (const float4*)g_feat;
    int col = r * 32 + lane;                         // f4 column in the 512-f row

    for (int base = 0; base < num; base += 32) {
        int cnt = min(32, num - base);
        int sj = 0;
        float ex = 0.f, ey = 0.f;
        if (lane < cnt) {
            sj = g_src[beg + base + lane];
            float2 e2 = ((const float2*)g_es)[sj * 4 + r];
            ex = e2.x; ey = e2.y;
        }
        for (int j = 0; j < cnt; j++) {
            int s    = __shfl_sync(FULL, sj, j);
            float jx = __shfl_sync(FULL, ex, j);
            float jy = __shfl_sync(FULL, ey, j);
            float p0 = __expf(lrelu(jx + edv.x) - m0);
            float p1 = __expf(lrelu(jy + edv.y) - m1);
            den0 += p0; den1 += p1;
            float pl = (lane < 16) ? p0 : p1;
            float4 f = feat4[s * 128 + col];
            acc.x += pl * f.x; acc.y += pl * f.y;
            acc.z += pl * f.z; acc.w += pl * f.w;
        }
    }

    // self loop
    {
        float p0 = __expf(self0 - m0);
        float p1 = __expf(self1 - m1);
        den0 += p0; den1 += p1;
        float pl = (lane < 16) ? p0 : p1;
        float4 f = feat4[n * 128 + col];
        acc.x += pl * f.x; acc.y += pl * f.y;
        acc.z += pl * f.z; acc.w += pl * f.w;
    }

    float inv = 1.f / ((lane < 16) ? den0 : den1);
    float4 b = ((const float4*)bias)[col];
    ((float4*)g_agg)[n * 128 + col] =
        make_float4(acc.x * inv + b.x, acc.y * inv + b.y,
                    acc.z * inv + b.z, acc.w * inv + b.w);
}

// ---------------- K4: MLP (tanh) + residual + LayerNorm ---------------------
__global__ void k_mlp(const float* __restrict__ hin,
                      const float* __restrict__ W1, const float* __restrict__ b1,
                      const float* __restrict__ W2, const float* __restrict__ b2,
                      const float* __restrict__ lng, const float* __restrict__ lnb,
                      float* __restrict__ hout)
{
    __shared__ float As[64][64];
    __shared__ float Ws[64][64];
    __shared__ float Zs[64][64];
    const int tid = threadIdx.x;
    const int tx = tid & 15, ty = tid >> 4;
    const int nb = blockIdx.x * 64;
    float4* As4 = (float4*)As;
    float4* Ws4 = (float4*)Ws;
    float4* Zs4 = (float4*)Zs;

    float4 acc[4];
    #pragma unroll
    for (int j = 0; j < 4; j++) acc[j] = make_float4(0.f, 0.f, 0.f, 0.f);

    for (int kc = 0; kc < 9; kc++) {
        #pragma unroll
        for (int i = 0; i < 4; i++) {
            int f = tid + i * 256;
            int row = f >> 4, c = f & 15;
            int n = nb + row;
            float4 v = make_float4(0.f, 0.f, 0.f, 0.f);
            if (n < NN) {
                v = (kc == 0) ? ((const float4*)hin)[n * 16 + c]
                              : ((const float4*)g_agg)[n * 128 + (kc - 1) * 16 + c];
            }
            As4[f] = v;
        }
        #pragma unroll
        for (int i = 0; i < 4; i++) {
            int f = tid + i * 256;
            Ws4[f] = ((const float4*)W1)[kc * 1024 + f];
        }
        __syncthreads();
        #pragma unroll
        for (int k = 0; k < 64; k++) {
            float4 wv = Ws4[k * 16 + tx];
            #pragma unroll
            for (int j = 0; j < 4; j++) {
                float a = As[ty * 4 + j][k];
                acc[j].x += a * wv.x; acc[j].y += a * wv.y;
                acc[j].z += a * wv.z; acc[j].w += a * wv.w;
            }
        }
        __syncthreads();
    }
    float4 bv = ((const float4*)b1)[tx];
    #pragma unroll
    for (int j = 0; j < 4; j++) {
        float4 z;
        z.x = tanhf(acc[j].x + bv.x);
        z.y = tanhf(acc[j].y + bv.y);
        z.z = tanhf(acc[j].z + bv.z);
        z.w = tanhf(acc[j].w + bv.w);
        Zs4[(ty * 4 + j) * 16 + tx] = z;
    }
    #pragma unroll
    for (int i = 0; i < 4; i++) {
        int f = tid + i * 256;
        Ws4[f] = ((const float4*)W2)[f];
    }
    __syncthreads();

    float4 a2[4];
    #pragma unroll
    for (int j = 0; j < 4; j++) a2[j] = make_float4(0.f, 0.f, 0.f, 0.f);
    #pragma unroll
    for (int k = 0; k < 64; k++) {
        float4 wv = Ws4[k * 16 + tx];
        #pragma unroll
        for (int j = 0; j < 4; j++) {
            float a = Zs[ty * 4 + j][k];
            a2[j].x += a * wv.x; a2[j].y += a * wv.y;
            a2[j].z += a * wv.z; a2[j].w += a * wv.w;
        }
    }
    __syncthreads();

    float4 b2v = ((const float4*)b2)[tx];
    #pragma unroll
    for (int j = 0; j < 4; j++) {
        int n = nb + ty * 4 + j;
        float4 res = (n < NN) ? ((const float4*)hin)[n * 16 + tx]
                              : make_float4(0.f, 0.f, 0.f, 0.f);
        float4 z;
        z.x = a2[j].x + b2v.x + res.x;
        z.y = a2[j].y + b2v.y + res.y;
        z.z = a2[j].z + b2v.z + res.z;
        z.w = a2[j].w + b2v.w + res.w;
        Zs4[(ty * 4 + j) * 16 + tx] = z;
    }
    __syncthreads();

    int lane = tid & 31, wpid = tid >> 5;
    for (int row = wpid; row < 64; row += 8) {
        float v0 = Zs[row][lane], v1 = Zs[row][lane + 32];
        float s = v0 + v1, q = v0 * v0 + v1 * v1;
        #pragma unroll
        for (int o = 16; o; o >>= 1) {
            s += __shfl_xor_sync(0xffffffffu, s, o);
            q += __shfl_xor_sync(0xffffffffu, q, o);
        }
        float mu = s * (1.f / 64.f);
        float var = q * (1.f / 64.f) - mu * mu;
        float rs = rsqrtf(var + LN_EPS);
        int n = nb + row;
        if (n < NN) {
            hout[n * 64 + lane]      = (v0 - mu) * rs * lng[lane] + lnb[lane];
            hout[n * 64 + lane + 32] = (v1 - mu) * rs * lng[lane + 32] + lnb[lane + 32];
        }
    }
}

// ---------------- launch -----------------------------------------------------
extern "C" void kernel_launch(void* const* d_in, const int* in_sizes, int n_in,
                              void* d_out, int out_size)
{
    const float* x   = (const float*)d_in[0];
    const int*   ei  = (const int*)  d_in[1];
    const float* ew  = (const float*)d_in[2];
    const float* gW  = (const float*)d_in[3];
    const float* gas = (const float*)d_in[4];
    const float* gad = (const float*)d_in[5];
    const float* gb  = (const float*)d_in[6];
    const float* W1  = (const float*)d_in[7];
    const float* b1  = (const float*)d_in[8];
    const float* W2  = (const float*)d_in[9];
    const float* b2  = (const float*)d_in[10];
    const float* lng = (const float*)d_in[11];
    const float* lnb = (const float*)d_in[12];
    float* out = (float*)d_out;

    float* hptr = nullptr;
    cudaGetSymbolAddress((void**)&hptr, g_h);

    const int NT  = (NN + 63) / 64;
    const int EB  = (EE + 255) / 256;
    const int KB  = (KEYS + 255) / 256;

    // ---- CSR build (graph fixed across layers) ----
    k_zero <<<KB, 256>>>();
    k_count<<<EB, 256>>>(ei, ew);
    k_scan1<<<SCAN_NBLK, SCAN_B>>>();
    k_scan2<<<1, 32>>>();
    k_scan3<<<KB, 256>>>();
    k_fill <<<EB, 256>>>(ei, ew);

    for (int l = 0; l < LL; l++) {
        const float* hin  = (l == 0) ? x : hptr;
        float*       hout = (l == 0) ? hptr : out;

        k_feat  <<<dim3(NT, RR), 256>>>(hin, gW + l * RR * 64 * 128);
        k_scores<<<NN, 256>>>(gas + l * RR * HH * CC, gad + l * RR * HH * CC);
        k_gat   <<<(KEYS + 7) / 8, 256>>>(gb + l * RR * HCC);
        k_mlp   <<<NT, 256>>>(hin,
                              W1 + l * 576 * 64, b1 + l * 64,
                              W2 + l * 64 * 64,  b2 + l * 64,
                              lng + l * 64, lnb + l * 64, hout);
    }
}

// round 5
// speedup vs baseline: 1.5784x; 1.1792x over previous
#include <cuda_runtime.h>
#include <cuda_bf16.h>
#include <math.h>

#define NN 50000
#define EE 400000
#define RR 4
#define HH 2
#define CC 64
#define HCC 128   // H*C
#define RHC 512   // R*H*C
#define LL 2
#define LN_EPS 1e-5f
#define SLOPE 0.2f

#define KEYS (NN * RR)          // 200000 (node, relation) segments
#define SCAN_B 1024
#define SCAN_NBLK ((KEYS + SCAN_B - 1) / SCAN_B)   // 196

// ---------------- scratch (device globals; no allocations allowed) ----------
__device__ float g_feat[NN * RHC];   // [n][r*128 + h*64 + c]
__device__ float g_agg [NN * RHC];   // GAT outputs (post softmax-agg + bias)
__device__ float g_es  [NN * 8];     // [n][r*2+h]
__device__ float g_ed  [NN * 8];
__device__ float g_h   [NN * 64];    // hidden state between layers
// CSR (built once per call; graph identical across layers)
__device__ int   g_cnt[KEYS];
__device__ int   g_off[KEYS];
__device__ int   g_cur[KEYS];
__device__ int   g_bsum[SCAN_NBLK];
__device__ int   g_src[2 * EE];

__device__ __forceinline__ float lrelu(float x) { return x > 0.f ? x : SLOPE * x; }

// ================= CSR build =================================================
__global__ void k_zero()
{
    int i = blockIdx.x * blockDim.x + threadIdx.x;
    if (i < KEYS) g_cnt[i] = 0;
}

__global__ void k_count(const int* __restrict__ ei, const float* __restrict__ ew)
{
    int e = blockIdx.x * blockDim.x + threadIdx.x;
    if (e >= EE) return;
    int s = ei[e], d = ei[EE + e];
    float w = ew[e];
    if (w == 0.f) return;
    int r0 = (w > 0.f) ? 0 : 2;
    atomicAdd(&g_cnt[d * 4 + r0], 1);
    atomicAdd(&g_cnt[s * 4 + r0 + 1], 1);
}

__global__ void k_scan1()
{
    __shared__ int sh[SCAN_B];
    int tid = threadIdx.x;
    int i = blockIdx.x * SCAN_B + tid;
    int v = (i < KEYS) ? g_cnt[i] : 0;
    sh[tid] = v;
    __syncthreads();
    #pragma unroll
    for (int off = 1; off < SCAN_B; off <<= 1) {
        int t = (tid >= off) ? sh[tid - off] : 0;
        __syncthreads();
        sh[tid] += t;
        __syncthreads();
    }
    if (i < KEYS) g_off[i] = sh[tid] - v;
    if (tid == SCAN_B - 1) g_bsum[blockIdx.x] = sh[tid];
}

__global__ void k_scan2()   // parallel scan over the 196 block sums
{
    __shared__ int sh[256];
    int t = threadIdx.x;
    int v = (t < SCAN_NBLK) ? g_bsum[t] : 0;
    sh[t] = v;
    __syncthreads();
    #pragma unroll
    for (int off = 1; off < 256; off <<= 1) {
        int x = (t >= off) ? sh[t - off] : 0;
        __syncthreads();
        sh[t] += x;
        __syncthreads();
    }
    if (t < SCAN_NBLK) g_bsum[t] = sh[t] - v;   // exclusive
}

__global__ void k_scan3()
{
    int i = blockIdx.x * blockDim.x + threadIdx.x;
    if (i >= KEYS) return;
    int o = g_off[i] + g_bsum[i >> 10];
    g_off[i] = o;
    g_cur[i] = o;
}

__global__ void k_fill(const int* __restrict__ ei, const float* __restrict__ ew)
{
    int e = blockIdx.x * blockDim.x + threadIdx.x;
    if (e >= EE) return;
    int s = ei[e], d = ei[EE + e];
    float w = ew[e];
    if (w == 0.f) return;
    int r0 = (w > 0.f) ? 0 : 2;
    int p1 = atomicAdd(&g_cur[d * 4 + r0], 1);
    g_src[p1] = s;
    int p2 = atomicAdd(&g_cur[s * 4 + r0 + 1], 1);
    g_src[p2] = d;
}

// ================= bf16-split tensor-core feat GEMM + fused scores ===========
__device__ __forceinline__ void split2(float2 v, unsigned& hi, unsigned& lo)
{
    __nv_bfloat162 h = __floats2bfloat162_rn(v.x, v.y);
    float2 hf = __bfloat1622float2(h);
    __nv_bfloat162 l = __floats2bfloat162_rn(v.x - hf.x, v.y - hf.y);
    hi = *(unsigned*)&h;
    lo = *(unsigned*)&l;
}

__device__ __forceinline__ void mma16816(float* c, const unsigned* a,
                                         unsigned b0, unsigned b1)
{
    asm volatile(
        "mma.sync.aligned.m16n8k16.row.col.f32.bf16.bf16.f32 "
        "{%0,%1,%2,%3}, {%4,%5,%6,%7}, {%8,%9}, {%0,%1,%2,%3};"
        : "+f"(c[0]), "+f"(c[1]), "+f"(c[2]), "+f"(c[3])
        : "r"(a[0]), "r"(a[1]), "r"(a[2]), "r"(a[3]), "r"(b0), "r"(b1));
}

// Block: 128 nodes x 128 cols (one relation). 8 warps, warp = 16 node rows.
// feat = hin @ W_r  in bf16 hi/lo split (3 MMAs), fused es/ed score epilogue.
__global__ __launch_bounds__(256) void k_feat_mma(
    const float* __restrict__ hin, const float* __restrict__ W,
    const float* __restrict__ asrc, const float* __restrict__ adst)
{
    // W transposed [n][k], rows padded to 72 bf16 (36 words) for bank spread
    __shared__ __nv_bfloat16 Whi[128 * 72];
    __shared__ __nv_bfloat16 Wlo[128 * 72];
    __shared__ float s_as[128], s_ad[128];

    const int tid = threadIdx.x;
    const int r   = blockIdx.y;
    const int nb  = blockIdx.x * 128;

    const float* Wr = W + r * 64 * 128;     // [k][n]
    for (int i = tid; i < 64 * 128; i += 256) {
        int k = i >> 7, n = i & 127;
        float x = Wr[i];
        __nv_bfloat16 h = __float2bfloat16(x);
        float rem = x - __bfloat162float(h);
        Whi[n * 72 + k] = h;
        Wlo[n * 72 + k] = __float2bfloat16(rem);
    }
    if (tid < 128) {
        s_as[tid] = asrc[r * 128 + tid];
        s_ad[tid] = adst[r * 128 + tid];
    }
    __syncthreads();

    const int w = tid >> 5, l = tid & 31;
    const int g = l >> 2, q = l & 3;
    const int row0 = nb + w * 16 + g;       // rows row0 and row0+8
    const unsigned* Whi32 = (const unsigned*)Whi;
    const unsigned* Wlo32 = (const unsigned*)Wlo;

    float c[16][4];
    #pragma unroll
    for (int t = 0; t < 16; t++) {
        c[t][0] = 0.f; c[t][1] = 0.f; c[t][2] = 0.f; c[t][3] = 0.f;
    }

    const int ra = min(row0, NN - 1);
    const int rb = min(row0 + 8, NN - 1);

    #pragma unroll
    for (int ks = 0; ks < 4; ks++) {
        int c0 = ks * 16 + q * 2;
        float2 x00 = *(const float2*)(hin + ra * 64 + c0);
        float2 x10 = *(const float2*)(hin + rb * 64 + c0);
        float2 x01 = *(const float2*)(hin + ra * 64 + c0 + 8);
        float2 x11 = *(const float2*)(hin + rb * 64 + c0 + 8);
        unsigned ahi[4], alo[4];
        split2(x00, ahi[0], alo[0]);
        split2(x10, ahi[1], alo[1]);
        split2(x01, ahi[2], alo[2]);
        split2(x11, ahi[3], alo[3]);

        #pragma unroll
        for (int t = 0; t < 16; t++) {
            int base = (t * 8 + g) * 36 + ks * 8 + q;
            unsigned bh0 = Whi32[base], bh1 = Whi32[base + 4];
            unsigned bl0 = Wlo32[base], bl1 = Wlo32[base + 4];
            mma16816(c[t], ahi, bh0, bh1);
            mma16816(c[t], ahi, bl0, bl1);
            mma16816(c[t], alo, bh0, bh1);
        }
    }

    // ---- store feat ----
    const bool ok0 = row0 < NN, ok1 = (row0 + 8) < NN;
    float2* out2 = (float2*)g_feat;
    #pragma unroll
    for (int t = 0; t < 16; t++) {
        int colw = t * 4 + q;               // float2 index within 64
        if (ok0) out2[row0 * 256 + r * 64 + colw] = make_float2(c[t][0], c[t][1]);
        if (ok1) out2[(row0 + 8) * 256 + r * 64 + colw] = make_float2(c[t][2], c[t][3]);
    }

    // ---- fused scores: es/ed per (row, head) ----
    float es00 = 0.f, es01 = 0.f, es10 = 0.f, es11 = 0.f;   // es[row][head]
    float ed00 = 0.f, ed01 = 0.f, ed10 = 0.f, ed11 = 0.f;
    #pragma unroll
    for (int t = 0; t < 16; t++) {
        int col = t * 8 + q * 2;
        float a0 = s_as[col], a1 = s_as[col + 1];
        float d0 = s_ad[col], d1 = s_ad[col + 1];
        if (t < 8) {
            es00 += c[t][0] * a0 + c[t][1] * a1;
            ed00 += c[t][0] * d0 + c[t][1] * d1;
            es10 += c[t][2] * a0 + c[t][3] * a1;
            ed10 += c[t][2] * d0 + c[t][3] * d1;
        } else {
            es01 += c[t][0] * a0 + c[t][1] * a1;
            ed01 += c[t][0] * d0 + c[t][1] * d1;
            es11 += c[t][2] * a0 + c[t][3] * a1;
            ed11 += c[t][2] * d0 + c[t][3] * d1;
        }
    }
    const unsigned FULL = 0xffffffffu;
    #pragma unroll
    for (int o = 1; o <= 2; o <<= 1) {
        es00 += __shfl_xor_sync(FULL, es00, o);
        es01 += __shfl_xor_sync(FULL, es01, o);
        es10 += __shfl_xor_sync(FULL, es10, o);
        es11 += __shfl_xor_sync(FULL, es11, o);
        ed00 += __shfl_xor_sync(FULL, ed00, o);
        ed01 += __shfl_xor_sync(FULL, ed01, o);
        ed10 += __shfl_xor_sync(FULL, ed10, o);
        ed11 += __shfl_xor_sync(FULL, ed11, o);
    }
    if (q == 0) {
        if (ok0) {
            g_es[row0 * 8 + r * 2 + 0] = es00;
            g_es[row0 * 8 + r * 2 + 1] = es01;
            g_ed[row0 * 8 + r * 2 + 0] = ed00;
            g_ed[row0 * 8 + r * 2 + 1] = ed01;
        }
        if (ok1) {
            g_es[(row0 + 8) * 8 + r * 2 + 0] = es10;
            g_es[(row0 + 8) * 8 + r * 2 + 1] = es11;
            g_ed[(row0 + 8) * 8 + r * 2 + 0] = ed10;
            g_ed[(row0 + 8) * 8 + r * 2 + 1] = ed11;
        }
    }
}

// ---------------- fused GAT softmax + aggregation (no atomics) --------------
__global__ void k_gat(const float* __restrict__ bias)
{
    const unsigned FULL = 0xffffffffu;
    int key = blockIdx.x * 8 + (threadIdx.x >> 5);
    if (key >= KEYS) return;
    int lane = threadIdx.x & 31;
    int n = key >> 2, r = key & 3;

    int beg = g_off[key];
    int num = g_cnt[key];

    float2 edv = ((const float2*)g_ed)[n * 4 + r];
    float2 esn = ((const float2*)g_es)[n * 4 + r];
    float self0 = lrelu(esn.x + edv.x);
    float self1 = lrelu(esn.y + edv.y);

    float m0 = self0, m1 = self1;
    for (int i = lane; i < num; i += 32) {
        int s = g_src[beg + i];
        float2 e2 = ((const float2*)g_es)[s * 4 + r];
        m0 = fmaxf(m0, lrelu(e2.x + edv.x));
        m1 = fmaxf(m1, lrelu(e2.y + edv.y));
    }
    #pragma unroll
    for (int o = 16; o; o >>= 1) {
        m0 = fmaxf(m0, __shfl_xor_sync(FULL, m0, o));
        m1 = fmaxf(m1, __shfl_xor_sync(FULL, m1, o));
    }

    float den0 = 0.f, den1 = 0.f;
    float4 acc = make_float4(0.f, 0.f, 0.f, 0.f);
    const float4* feat4 = (const float4*)g_feat;
    int col = r * 32 + lane;

    for (int base = 0; base < num; base += 32) {
        int cnt = min(32, num - base);
        int sj = 0;
        float ex = 0.f, ey = 0.f;
        if (lane < cnt) {
            sj = g_src[beg + base + lane];
            float2 e2 = ((const float2*)g_es)[sj * 4 + r];
            ex = e2.x; ey = e2.y;
        }
        for (int j = 0; j < cnt; j++) {
            int s    = __shfl_sync(FULL, sj, j);
            float jx = __shfl_sync(FULL, ex, j);
            float jy = __shfl_sync(FULL, ey, j);
            float p0 = __expf(lrelu(jx + edv.x) - m0);
            float p1 = __expf(lrelu(jy + edv.y) - m1);
            den0 += p0; den1 += p1;
            float pl = (lane < 16) ? p0 : p1;
            float4 f = feat4[s * 128 + col];
            acc.x += pl * f.x; acc.y += pl * f.y;
            acc.z += pl * f.z; acc.w += pl * f.w;
        }
    }
    {
        float p0 = __expf(self0 - m0);
        float p1 = __expf(self1 - m1);
        den0 += p0; den1 += p1;
        float pl = (lane < 16) ? p0 : p1;
        float4 f = feat4[n * 128 + col];
        acc.x += pl * f.x; acc.y += pl * f.y;
        acc.z += pl * f.z; acc.w += pl * f.w;
    }

    float inv = 1.f / ((lane < 16) ? den0 : den1);
    float4 b = ((const float4*)bias)[col];
    ((float4*)g_agg)[n * 128 + col] =
        make_float4(acc.x * inv + b.x, acc.y * inv + b.y,
                    acc.z * inv + b.z, acc.w * inv + b.w);
}

// ---------------- MLP (tanh) + residual + LayerNorm -------------------------
__global__ void k_mlp(const float* __restrict__ hin,
                      const float* __restrict__ W1, const float* __restrict__ b1,
                      const float* __restrict__ W2, const float* __restrict__ b2,
                      const float* __restrict__ lng, const float* __restrict__ lnb,
                      float* __restrict__ hout)
{
    __shared__ float As[64][64];
    __shared__ float Ws[64][64];
    __shared__ float Zs[64][64];
    const int tid = threadIdx.x;
    const int tx = tid & 15, ty = tid >> 4;
    const int nb = blockIdx.x * 64;
    float4* As4 = (float4*)As;
    float4* Ws4 = (float4*)Ws;
    float4* Zs4 = (float4*)Zs;

    float4 acc[4];
    #pragma unroll
    for (int j = 0; j < 4; j++) acc[j] = make_float4(0.f, 0.f, 0.f, 0.f);

    for (int kc = 0; kc < 9; kc++) {
        #pragma unroll
        for (int i = 0; i < 4; i++) {
            int f = tid + i * 256;
            int row = f >> 4, col = f & 15;
            int n = nb + row;
            float4 v = make_float4(0.f, 0.f, 0.f, 0.f);
            if (n < NN) {
                v = (kc == 0) ? ((const float4*)hin)[n * 16 + col]
                              : ((const float4*)g_agg)[n * 128 + (kc - 1) * 16 + col];
            }
            As4[f] = v;
        }
        #pragma unroll
        for (int i = 0; i < 4; i++) {
            int f = tid + i * 256;
            Ws4[f] = ((const float4*)W1)[kc * 1024 + f];
        }
        __syncthreads();
        #pragma unroll
        for (int k = 0; k < 64; k++) {
            float4 wv = Ws4[k * 16 + tx];
            #pragma unroll
            for (int j = 0; j < 4; j++) {
                float a = As[ty * 4 + j][k];
                acc[j].x += a * wv.x; acc[j].y += a * wv.y;
                acc[j].z += a * wv.z; acc[j].w += a * wv.w;
            }
        }
        __syncthreads();
    }
    float4 bv = ((const float4*)b1)[tx];
    #pragma unroll
    for (int j = 0; j < 4; j++) {
        float4 z;
        z.x = tanhf(acc[j].x + bv.x);
        z.y = tanhf(acc[j].y + bv.y);
        z.z = tanhf(acc[j].z + bv.z);
        z.w = tanhf(acc[j].w + bv.w);
        Zs4[(ty * 4 + j) * 16 + tx] = z;
    }
    #pragma unroll
    for (int i = 0; i < 4; i++) {
        int f = tid + i * 256;
        Ws4[f] = ((const float4*)W2)[f];
    }
    __syncthreads();

    float4 a2[4];
    #pragma unroll
    for (int j = 0; j < 4; j++) a2[j] = make_float4(0.f, 0.f, 0.f, 0.f);
    #pragma unroll
    for (int k = 0; k < 64; k++) {
        float4 wv = Ws4[k * 16 + tx];
        #pragma unroll
        for (int j = 0; j < 4; j++) {
            float a = Zs[ty * 4 + j][k];
            a2[j].x += a * wv.x; a2[j].y += a * wv.y;
            a2[j].z += a * wv.z; a2[j].w += a * wv.w;
        }
    }
    __syncthreads();

    float4 b2v = ((const float4*)b2)[tx];
    #pragma unroll
    for (int j = 0; j < 4; j++) {
        int n = nb + ty * 4 + j;
        float4 res = (n < NN) ? ((const float4*)hin)[n * 16 + tx]
                              : make_float4(0.f, 0.f, 0.f, 0.f);
        float4 z;
        z.x = a2[j].x + b2v.x + res.x;
        z.y = a2[j].y + b2v.y + res.y;
        z.z = a2[j].z + b2v.z + res.z;
        z.w = a2[j].w + b2v.w + res.w;
        Zs4[(ty * 4 + j) * 16 + tx] = z;
    }
    __syncthreads();

    int lane = tid & 31, wpid = tid >> 5;
    for (int row = wpid; row < 64; row += 8) {
        float v0 = Zs[row][lane], v1 = Zs[row][lane + 32];
        float s = v0 + v1, qq = v0 * v0 + v1 * v1;
        #pragma unroll
        for (int o = 16; o; o >>= 1) {
            s  += __shfl_xor_sync(0xffffffffu, s, o);
            qq += __shfl_xor_sync(0xffffffffu, qq, o);
        }
        float mu = s * (1.f / 64.f);
        float var = qq * (1.f / 64.f) - mu * mu;
        float rs = rsqrtf(var + LN_EPS);
        int n = nb + row;
        if (n < NN) {
            hout[n * 64 + lane]      = (v0 - mu) * rs * lng[lane] + lnb[lane];
            hout[n * 64 + lane + 32] = (v1 - mu) * rs * lng[lane + 32] + lnb[lane + 32];
        }
    }
}

// ---------------- launch -----------------------------------------------------
extern "C" void kernel_launch(void* const* d_in, const int* in_sizes, int n_in,
                              void* d_out, int out_size)
{
    const float* x   = (const float*)d_in[0];
    const int*   ei  = (const int*)  d_in[1];
    const float* ew  = (const float*)d_in[2];
    const float* gW  = (const float*)d_in[3];
    const float* gas = (const float*)d_in[4];
    const float* gad = (const float*)d_in[5];
    const float* gb  = (const float*)d_in[6];
    const float* W1  = (const float*)d_in[7];
    const float* b1  = (const float*)d_in[8];
    const float* W2  = (const float*)d_in[9];
    const float* b2  = (const float*)d_in[10];
    const float* lng = (const float*)d_in[11];
    const float* lnb = (const float*)d_in[12];
    float* out = (float*)d_out;

    float* hptr = nullptr;
    cudaGetSymbolAddress((void**)&hptr, g_h);

    const int NT  = (NN + 63) / 64;
    const int EB  = (EE + 255) / 256;
    const int KB  = (KEYS + 255) / 256;
    const int FT  = (NN + 127) / 128;       // 391 feat tiles

    // ---- CSR build interleaved with layer-0 feat (feat at launch idx 3
    //      so ncu's fixed capture slot profiles the new MMA kernel) ----
    k_zero <<<KB, 256>>>();
    k_count<<<EB, 256>>>(ei, ew);
    k_scan1<<<SCAN_NBLK, SCAN_B>>>();
    k_feat_mma<<<dim3(FT, RR), 256>>>(x, gW, gas, gad);        // layer 0
    k_scan2<<<1, 256>>>();
    k_scan3<<<KB, 256>>>();
    k_fill <<<EB, 256>>>(ei, ew);

    // layer 0 tail
    k_gat<<<(KEYS + 7) / 8, 256>>>(gb);
    k_mlp<<<NT, 256>>>(x, W1, b1, W2, b2, lng, lnb, hptr);

    // layer 1
    k_feat_mma<<<dim3(FT, RR), 256>>>(hptr, gW + RR * 64 * 128,
                                      gas + RR * HH * CC, gad + RR * HH * CC);
    k_gat<<<(KEYS + 7) / 8, 256>>>(gb + RR * HCC);
    k_mlp<<<NT, 256>>>(hptr,
                       W1 + 576 * 64, b1 + 64,
                       W2 + 64 * 64,  b2 + 64,
                       lng + 64, lnb + 64, out);
}

// round 7
// speedup vs baseline: 1.7012x; 1.0778x over previous
#include <cuda_runtime.h>
#include <cuda_bf16.h>
#include <math.h>

#define NN 50000
#define EE 400000
#define RR 4
#define HH 2
#define CC 64
#define HCC 128   // H*C
#define RHC 512   // R*H*C
#define LL 2
#define LN_EPS 1e-5f
#define SLOPE 0.2f

#define KEYS (NN * RR)          // 200000 (node, relation) segments
#define SCAN_B 1024
#define SCAN_NBLK ((KEYS + SCAN_B - 1) / SCAN_B)   // 196

// ---------------- scratch (device globals; no allocations allowed) ----------
__device__ float g_feat[NN * RHC];   // [n][r*128 + h*64 + c]
__device__ float g_agg [NN * RHC];   // GAT outputs (post softmax-agg + bias)
__device__ float g_es  [NN * 8];     // [n][r*2+h]
__device__ float g_ed  [NN * 8];
__device__ float g_h   [NN * 64];    // hidden state between layers
// CSR (built once per call; graph identical across layers)
__device__ int   g_cnt[KEYS];
__device__ int   g_off[KEYS];
__device__ int   g_cur[KEYS];
__device__ int   g_bsum[SCAN_NBLK];
__device__ int   g_src[2 * EE];
// pre-split MLP weights in MMA fragment word layout
// W1: [l][chunk(9)][n(64)][36 words]  (words 0..31 used, 32..35 pad)
__device__ unsigned g_w1hi[LL * 9 * 64 * 36];
__device__ unsigned g_w1lo[LL * 9 * 64 * 36];
__device__ unsigned g_w2hi[LL * 64 * 36];
__device__ unsigned g_w2lo[LL * 64 * 36];

__device__ __forceinline__ float lrelu(float x) { return x > 0.f ? x : SLOPE * x; }

__device__ __forceinline__ void split2(float2 v, unsigned& hi, unsigned& lo)
{
    __nv_bfloat162 h = __floats2bfloat162_rn(v.x, v.y);
    float2 hf = __bfloat1622float2(h);
    __nv_bfloat162 l = __floats2bfloat162_rn(v.x - hf.x, v.y - hf.y);
    hi = *(unsigned*)&h;
    lo = *(unsigned*)&l;
}

__device__ __forceinline__ void mma16816(float* c, const unsigned* a,
                                         unsigned b0, unsigned b1)
{
    asm volatile(
        "mma.sync.aligned.m16n8k16.row.col.f32.bf16.bf16.f32 "
        "{%0,%1,%2,%3}, {%4,%5,%6,%7}, {%8,%9}, {%0,%1,%2,%3};"
        : "+f"(c[0]), "+f"(c[1]), "+f"(c[2]), "+f"(c[3])
        : "r"(a[0]), "r"(a[1]), "r"(a[2]), "r"(a[3]), "r"(b0), "r"(b1));
}

// ================= CSR build =================================================
__global__ void k_zero()
{
    int i = blockIdx.x * blockDim.x + threadIdx.x;
    if (i < KEYS) g_cnt[i] = 0;
}

__global__ void k_count(const int* __restrict__ ei, const float* __restrict__ ew)
{
    int e = blockIdx.x * blockDim.x + threadIdx.x;
    if (e >= EE) return;
    int s = ei[e], d = ei[EE + e];
    float w = ew[e];
    if (w == 0.f) return;
    int r0 = (w > 0.f) ? 0 : 2;
    atomicAdd(&g_cnt[d * 4 + r0], 1);
    atomicAdd(&g_cnt[s * 4 + r0 + 1], 1);
}

__global__ void k_scan1()
{
    __shared__ int sh[SCAN_B];
    int tid = threadIdx.x;
    int i = blockIdx.x * SCAN_B + tid;
    int v = (i < KEYS) ? g_cnt[i] : 0;
    sh[tid] = v;
    __syncthreads();
    #pragma unroll
    for (int off = 1; off < SCAN_B; off <<= 1) {
        int t = (tid >= off) ? sh[tid - off] : 0;
        __syncthreads();
        sh[tid] += t;
        __syncthreads();
    }
    if (i < KEYS) g_off[i] = sh[tid] - v;
    if (tid == SCAN_B - 1) g_bsum[blockIdx.x] = sh[tid];
}

__global__ void k_scan2()
{
    __shared__ int sh[256];
    int t = threadIdx.x;
    int v = (t < SCAN_NBLK) ? g_bsum[t] : 0;
    sh[t] = v;
    __syncthreads();
    #pragma unroll
    for (int off = 1; off < 256; off <<= 1) {
        int x = (t >= off) ? sh[t - off] : 0;
        __syncthreads();
        sh[t] += x;
        __syncthreads();
    }
    if (t < SCAN_NBLK) g_bsum[t] = sh[t] - v;
}

__global__ void k_scan3()
{
    int i = blockIdx.x * blockDim.x + threadIdx.x;
    if (i >= KEYS) return;
    int o = g_off[i] + g_bsum[i >> 10];
    g_off[i] = o;
    g_cur[i] = o;
}

__global__ void k_fill(const int* __restrict__ ei, const float* __restrict__ ew)
{
    int e = blockIdx.x * blockDim.x + threadIdx.x;
    if (e >= EE) return;
    int s = ei[e], d = ei[EE + e];
    float w = ew[e];
    if (w == 0.f) return;
    int r0 = (w > 0.f) ? 0 : 2;
    int p1 = atomicAdd(&g_cur[d * 4 + r0], 1);
    g_src[p1] = s;
    int p2 = atomicAdd(&g_cur[s * 4 + r0 + 1], 1);
    g_src[p2] = d;
}

// ================= weight pre-split for MLP MMA ==============================
// word wd = ks*8 + j : j<4 -> k = ks*16 + j*2 ; j>=4 -> k = ks*16 + 8 + (j-4)*2
__global__ void k_split(const float* __restrict__ W1, const float* __restrict__ W2)
{
    int i = blockIdx.x * blockDim.x + threadIdx.x;
    if (i < LL * 9 * 64 * 32) {
        int l   = i / (9 * 64 * 32);
        int rm  = i % (9 * 64 * 32);
        int ch  = rm / 2048;
        int rm2 = rm % 2048;
        int n   = rm2 >> 5;
        int wd  = rm2 & 31;
        int ks = wd >> 3, j = wd & 7;
        int k = ch * 64 + ks * 16 + ((j < 4) ? j * 2 : 8 + (j - 4) * 2);
        const float* Wl = W1 + l * 576 * 64;
        unsigned hi, lo;
        split2(make_float2(Wl[k * 64 + n], Wl[(k + 1) * 64 + n]), hi, lo);
        int out = ((l * 9 + ch) * 64 + n) * 36 + wd;
        g_w1hi[out] = hi;
        g_w1lo[out] = lo;
    } else if (i < LL * 9 * 64 * 32 + LL * 64 * 32) {
        int i2  = i - LL * 9 * 64 * 32;
        int l   = i2 / 2048;
        int rm2 = i2 % 2048;
        int n   = rm2 >> 5;
        int wd  = rm2 & 31;
        int ks = wd >> 3, j = wd & 7;
        int k = ks * 16 + ((j < 4) ? j * 2 : 8 + (j - 4) * 2);
        const float* Wl = W2 + l * 64 * 64;
        unsigned hi, lo;
        split2(make_float2(Wl[k * 64 + n], Wl[(k + 1) * 64 + n]), hi, lo);
        int out = (l * 64 + n) * 36 + wd;
        g_w2hi[out] = hi;
        g_w2lo[out] = lo;
    }
}

// ================= bf16-split tensor-core feat GEMM + fused scores ===========
__global__ __launch_bounds__(256) void k_feat_mma(
    const float* __restrict__ hin, const float* __restrict__ W,
    const float* __restrict__ asrc, const float* __restrict__ adst)
{
    __shared__ __nv_bfloat16 Whi[128 * 72];
    __shared__ __nv_bfloat16 Wlo[128 * 72];
    __shared__ float s_as[128], s_ad[128];

    const int tid = threadIdx.x;
    const int r   = blockIdx.y;
    const int nb  = blockIdx.x * 128;

    const float* Wr = W + r * 64 * 128;
    for (int i = tid; i < 64 * 128; i += 256) {
        int k = i >> 7, n = i & 127;
        float x = Wr[i];
        __nv_bfloat16 h = __float2bfloat16(x);
        float rem = x - __bfloat162float(h);
        Whi[n * 72 + k] = h;
        Wlo[n * 72 + k] = __float2bfloat16(rem);
    }
    if (tid < 128) {
        s_as[tid] = asrc[r * 128 + tid];
        s_ad[tid] = adst[r * 128 + tid];
    }
    __syncthreads();

    const int w = tid >> 5, l = tid & 31;
    const int g = l >> 2, q = l & 3;
    const int row0 = nb + w * 16 + g;
    const unsigned* Whi32 = (const unsigned*)Whi;
    const unsigned* Wlo32 = (const unsigned*)Wlo;

    float c[16][4];
    #pragma unroll
    for (int t = 0; t < 16; t++) {
        c[t][0] = 0.f; c[t][1] = 0.f; c[t][2] = 0.f; c[t][3] = 0.f;
    }

    const int ra = min(row0, NN - 1);
    const int rb = min(row0 + 8, NN - 1);

    #pragma unroll
    for (int ks = 0; ks < 4; ks++) {
        int c0 = ks * 16 + q * 2;
        float2 x00 = *(const float2*)(hin + ra * 64 + c0);
        float2 x10 = *(const float2*)(hin + rb * 64 + c0);
        float2 x01 = *(const float2*)(hin + ra * 64 + c0 + 8);
        float2 x11 = *(const float2*)(hin + rb * 64 + c0 + 8);
        unsigned ahi[4], alo[4];
        split2(x00, ahi[0], alo[0]);
        split2(x10, ahi[1], alo[1]);
        split2(x01, ahi[2], alo[2]);
        split2(x11, ahi[3], alo[3]);

        #pragma unroll
        for (int t = 0; t < 16; t++) {
            int base = (t * 8 + g) * 36 + ks * 8 + q;
            unsigned bh0 = Whi32[base], bh1 = Whi32[base + 4];
            unsigned bl0 = Wlo32[base], bl1 = Wlo32[base + 4];
            mma16816(c[t], ahi, bh0, bh1);
            mma16816(c[t], ahi, bl0, bl1);
            mma16816(c[t], alo, bh0, bh1);
        }
    }

    const bool ok0 = row0 < NN, ok1 = (row0 + 8) < NN;
    float2* out2 = (float2*)g_feat;
    #pragma unroll
    for (int t = 0; t < 16; t++) {
        int colw = t * 4 + q;
        if (ok0) out2[row0 * 256 + r * 64 + colw] = make_float2(c[t][0], c[t][1]);
        if (ok1) out2[(row0 + 8) * 256 + r * 64 + colw] = make_float2(c[t][2], c[t][3]);
    }

    float es00 = 0.f, es01 = 0.f, es10 = 0.f, es11 = 0.f;
    float ed00 = 0.f, ed01 = 0.f, ed10 = 0.f, ed11 = 0.f;
    #pragma unroll
    for (int t = 0; t < 16; t++) {
        int col = t * 8 + q * 2;
        float a0 = s_as[col], a1 = s_as[col + 1];
        float d0 = s_ad[col], d1 = s_ad[col + 1];
        if (t < 8) {
            es00 += c[t][0] * a0 + c[t][1] * a1;
            ed00 += c[t][0] * d0 + c[t][1] * d1;
            es10 += c[t][2] * a0 + c[t][3] * a1;
            ed10 += c[t][2] * d0 + c[t][3] * d1;
        } else {
            es01 += c[t][0] * a0 + c[t][1] * a1;
            ed01 += c[t][0] * d0 + c[t][1] * d1;
            es11 += c[t][2] * a0 + c[t][3] * a1;
            ed11 += c[t][2] * d0 + c[t][3] * d1;
        }
    }
    const unsigned FULL = 0xffffffffu;
    #pragma unroll
    for (int o = 1; o <= 2; o <<= 1) {
        es00 += __shfl_xor_sync(FULL, es00, o);
        es01 += __shfl_xor_sync(FULL, es01, o);
        es10 += __shfl_xor_sync(FULL, es10, o);
        es11 += __shfl_xor_sync(FULL, es11, o);
        ed00 += __shfl_xor_sync(FULL, ed00, o);
        ed01 += __shfl_xor_sync(FULL, ed01, o);
        ed10 += __shfl_xor_sync(FULL, ed10, o);
        ed11 += __shfl_xor_sync(FULL, ed11, o);
    }
    if (q == 0) {
        if (ok0) {
            g_es[row0 * 8 + r * 2 + 0] = es00;
            g_es[row0 * 8 + r * 2 + 1] = es01;
            g_ed[row0 * 8 + r * 2 + 0] = ed00;
            g_ed[row0 * 8 + r * 2 + 1] = ed01;
        }
        if (ok1) {
            g_es[(row0 + 8) * 8 + r * 2 + 0] = es10;
            g_es[(row0 + 8) * 8 + r * 2 + 1] = es11;
            g_ed[(row0 + 8) * 8 + r * 2 + 0] = ed10;
            g_ed[(row0 + 8) * 8 + r * 2 + 1] = ed11;
        }
    }
}

// ---------------- fused GAT softmax + aggregation (no atomics) --------------
__global__ void k_gat(const float* __restrict__ bias)
{
    const unsigned FULL = 0xffffffffu;
    int key = blockIdx.x * 8 + (threadIdx.x >> 5);
    if (key >= KEYS) return;
    int lane = threadIdx.x & 31;
    int n = key >> 2, r = key & 3;

    int beg = g_off[key];
    int num = g_cnt[key];

    float2 edv = ((const float2*)g_ed)[n * 4 + r];
    float2 esn = ((const float2*)g_es)[n * 4 + r];
    float self0 = lrelu(esn.x + edv.x);
    float self1 = lrelu(esn.y + edv.y);

    float m0 = self0, m1 = self1;
    for (int i = lane; i < num; i += 32) {
        int s = g_src[beg + i];
        float2 e2 = ((const float2*)g_es)[s * 4 + r];
        m0 = fmaxf(m0, lrelu(e2.x + edv.x));
        m1 = fmaxf(m1, lrelu(e2.y + edv.y));
    }
    #pragma unroll
    for (int o = 16; o; o >>= 1) {
        m0 = fmaxf(m0, __shfl_xor_sync(FULL, m0, o));
        m1 = fmaxf(m1, __shfl_xor_sync(FULL, m1, o));
    }

    float den0 = 0.f, den1 = 0.f;
    float4 acc = make_float4(0.f, 0.f, 0.f, 0.f);
    const float4* feat4 = (const float4*)g_feat;
    int col = r * 32 + lane;

    for (int base = 0; base < num; base += 32) {
        int cnt = min(32, num - base);
        int sj = 0;
        float ex = 0.f, ey = 0.f;
        if (lane < cnt) {
            sj = g_src[beg + base + lane];
            float2 e2 = ((const float2*)g_es)[sj * 4 + r];
            ex = e2.x; ey = e2.y;
        }
        for (int j = 0; j < cnt; j++) {
            int s    = __shfl_sync(FULL, sj, j);
            float jx = __shfl_sync(FULL, ex, j);
            float jy = __shfl_sync(FULL, ey, j);
            float p0 = __expf(lrelu(jx + edv.x) - m0);
            float p1 = __expf(lrelu(jy + edv.y) - m1);
            den0 += p0; den1 += p1;
            float pl = (lane < 16) ? p0 : p1;
            float4 f = feat4[s * 128 + col];
            acc.x += pl * f.x; acc.y += pl * f.y;
            acc.z += pl * f.z; acc.w += pl * f.w;
        }
    }
    {
        float p0 = __expf(self0 - m0);
        float p1 = __expf(self1 - m1);
        den0 += p0; den1 += p1;
        float pl = (lane < 16) ? p0 : p1;
        float4 f = feat4[n * 128 + col];
        acc.x += pl * f.x; acc.y += pl * f.y;
        acc.z += pl * f.z; acc.w += pl * f.w;
    }

    float inv = 1.f / ((lane < 16) ? den0 : den1);
    float4 b = ((const float4*)bias)[col];
    ((float4*)g_agg)[n * 128 + col] =
        make_float4(acc.x * inv + b.x, acc.y * inv + b.y,
                    acc.z * inv + b.z, acc.w * inv + b.w);
}

// ================= MLP via bf16-split MMA + fused residual/LN ================
// Block = 128 nodes, 8 warps (warp = 16 rows). GEMM1 [128x576]@[576x64] ->
// tanh -> GEMM2 [128x64]@[64x64] -> +b2 +residual -> LayerNorm -> hout.
__global__ __launch_bounds__(256) void k_mlp_mma(
    const float* __restrict__ hin, int l,
    const float* __restrict__ b1, const float* __restrict__ b2,
    const float* __restrict__ lng, const float* __restrict__ lnb,
    float* __restrict__ hout)
{
    __shared__ unsigned sWhi[64 * 36];
    __shared__ unsigned sWlo[64 * 36];
    __shared__ float s_b1[64], s_b2[64], s_lng[64], s_lnb[64];

    const int tid = threadIdx.x;
    const int w = tid >> 5, ln = tid & 31;
    const int g = ln >> 2, q = ln & 3;
    const int nb = blockIdx.x * 128;
    const int row0 = nb + w * 16 + g;
    const int ra = min(row0, NN - 1);
    const int rb = min(row0 + 8, NN - 1);

    if (tid < 64) {
        s_b1[tid]  = b1[tid];
        s_b2[tid]  = b2[tid];
        s_lng[tid] = lng[tid];
        s_lnb[tid] = lnb[tid];
    }

    float c1[8][4];
    #pragma unroll
    for (int t = 0; t < 8; t++) {
        c1[t][0] = 0.f; c1[t][1] = 0.f; c1[t][2] = 0.f; c1[t][3] = 0.f;
    }

    const unsigned* w1hi = g_w1hi + l * 9 * 2304;
    const unsigned* w1lo = g_w1lo + l * 9 * 2304;

    for (int ch = 0; ch < 9; ch++) {
        __syncthreads();
        for (int i = tid; i < 2304; i += 256) {
            sWhi[i] = w1hi[ch * 2304 + i];
            sWlo[i] = w1lo[ch * 2304 + i];
        }
        __syncthreads();

        #pragma unroll
        for (int ks = 0; ks < 4; ks++) {
            float2 x00, x10, x01, x11;
            if (ch == 0) {
                int c0 = ks * 16 + q * 2;
                x00 = *(const float2*)(hin + ra * 64 + c0);
                x10 = *(const float2*)(hin + rb * 64 + c0);
                x01 = *(const float2*)(hin + ra * 64 + c0 + 8);
                x11 = *(const float2*)(hin + rb * 64 + c0 + 8);
            } else {
                int c0 = (ch - 1) * 64 + ks * 16 + q * 2;
                x00 = *(const float2*)(g_agg + ra * 512 + c0);
                x10 = *(const float2*)(g_agg + rb * 512 + c0);
                x01 = *(const float2*)(g_agg + ra * 512 + c0 + 8);
                x11 = *(const float2*)(g_agg + rb * 512 + c0 + 8);
            }
            unsigned ahi[4], alo[4];
            split2(x00, ahi[0], alo[0]);
            split2(x10, ahi[1], alo[1]);
            split2(x01, ahi[2], alo[2]);
            split2(x11, ahi[3], alo[3]);

            #pragma unroll
            for (int t = 0; t < 8; t++) {
                int base = (t * 8 + g) * 36 + ks * 8 + q;
                unsigned bh0 = sWhi[base], bh1 = sWhi[base + 4];
                unsigned bl0 = sWlo[base], bl1 = sWlo[base + 4];
                mma16816(c1[t], ahi, bh0, bh1);
                mma16816(c1[t], ahi, bl0, bl1);
                mma16816(c1[t], alo, bh0, bh1);
            }
        }
    }

    // ---- tanh + bias -> Z, re-split into A fragments for GEMM2 ----
    unsigned ahi2[4][4], alo2[4][4];
    #pragma unroll
    for (int t = 0; t < 8; t++) {
        int col0 = t * 8 + q * 2;
        float z0 = tanhf(c1[t][0] + s_b1[col0]);
        float z1 = tanhf(c1[t][1] + s_b1[col0 + 1]);
        float z2 = tanhf(c1[t][2] + s_b1[col0]);
        float z3 = tanhf(c1[t][3] + s_b1[col0 + 1]);
        int kt = t >> 1;
        int o = (t & 1) ? 2 : 0;
        split2(make_float2(z0, z1), ahi2[kt][o + 0], alo2[kt][o + 0]);
        split2(make_float2(z2, z3), ahi2[kt][o + 1], alo2[kt][o + 1]);
    }
    // NOTE: fragment order within a k-tile must be a0(row g,k..),a1(row g+8,k..),
    // a2(row g, k+8..), a3(row g+8, k+8..). t even -> a0,a1 ; t odd -> a2,a3. ok.

    __syncthreads();
    for (int i = tid; i < 2304; i += 256) {
        sWhi[i] = g_w2hi[l * 2304 + i];
        sWlo[i] = g_w2lo[l * 2304 + i];
    }
    __syncthreads();

    float c2[8][4];
    #pragma unroll
    for (int t = 0; t < 8; t++) {
        c2[t][0] = 0.f; c2[t][1] = 0.f; c2[t][2] = 0.f; c2[t][3] = 0.f;
    }
    #pragma unroll
    for (int kt = 0; kt < 4; kt++) {
        #pragma unroll
        for (int t = 0; t < 8; t++) {
            int base = (t * 8 + g) * 36 + kt * 8 + q;
            unsigned bh0 = sWhi[base], bh1 = sWhi[base + 4];
            unsigned bl0 = sWlo[base], bl1 = sWlo[base + 4];
            mma16816(c2[t], ahi2[kt], bh0, bh1);
            mma16816(c2[t], ahi2[kt], bl0, bl1);
            mma16816(c2[t], alo2[kt], bh0, bh1);
        }
    }

    // ---- +b2 +residual, LayerNorm, store ----
    float v[8][4];
    float sA = 0.f, qA = 0.f, sB = 0.f, qB = 0.f;
    #pragma unroll
    for (int t = 0; t < 8; t++) {
        int col0 = t * 8 + q * 2;
        float2 r0 = *(const float2*)(hin + ra * 64 + col0);
        float2 r1 = *(const float2*)(hin + rb * 64 + col0);
        v[t][0] = c2[t][0] + s_b2[col0]     + r0.x;
        v[t][1] = c2[t][1] + s_b2[col0 + 1] + r0.y;
        v[t][2] = c2[t][2] + s_b2[col0]     + r1.x;
        v[t][3] = c2[t][3] + s_b2[col0 + 1] + r1.y;
        sA += v[t][0] + v[t][1];
        qA += v[t][0] * v[t][0] + v[t][1] * v[t][1];
        sB += v[t][2] + v[t][3];
        qB += v[t][2] * v[t][2] + v[t][3] * v[t][3];
    }
    const unsigned FULL = 0xffffffffu;
    #pragma unroll
    for (int o = 1; o <= 2; o <<= 1) {
        sA += __shfl_xor_sync(FULL, sA, o);
        qA += __shfl_xor_sync(FULL, qA, o);
        sB += __shfl_xor_sync(FULL, sB, o);
        qB += __shfl_xor_sync(FULL, qB, o);
    }
    float muA = sA * (1.f / 64.f);
    float rsA = rsqrtf(qA * (1.f / 64.f) - muA * muA + LN_EPS);
    float muB = sB * (1.f / 64.f);
    float rsB = rsqrtf(qB * (1.f / 64.f) - muB * muB + LN_EPS);

    const bool ok0 = row0 < NN, ok1 = (row0 + 8) < NN;
    #pragma unroll
    for (int t = 0; t < 8; t++) {
        int col0 = t * 8 + q * 2;
        float g0 = s_lng[col0], g1 = s_lng[col0 + 1];
        float o0 = s_lnb[col0], o1 = s_lnb[col0 + 1];
        if (ok0)
            *(float2*)(hout + row0 * 64 + col0) =
                make_float2((v[t][0] - muA) * rsA * g0 + o0,
                            (v[t][1] - muA) * rsA * g1 + o1);
        if (ok1)
            *(float2*)(hout + (row0 + 8) * 64 + col0) =
                make_float2((v[t][2] - muB) * rsB * g0 + o0,
                            (v[t][3] - muB) * rsB * g1 + o1);
    }
}

// ---------------- launch -----------------------------------------------------
extern "C" void kernel_launch(void* const* d_in, const int* in_sizes, int n_in,
                              void* d_out, int out_size)
{
    const float* x   = (const float*)d_in[0];
    const int*   ei  = (const int*)  d_in[1];
    const float* ew  = (const float*)d_in[2];
    const float* gW  = (const float*)d_in[3];
    const float* gas = (const float*)d_in[4];
    const float* gad = (const float*)d_in[5];
    const float* gb  = (const float*)d_in[6];
    const float* W1  = (const float*)d_in[7];
    const float* b1  = (const float*)d_in[8];
    const float* W2  = (const float*)d_in[9];
    const float* b2  = (const float*)d_in[10];
    const float* lng = (const float*)d_in[11];
    const float* lnb = (const float*)d_in[12];
    float* out = (float*)d_out;

    float* hptr = nullptr;
    cudaGetSymbolAddress((void**)&hptr, g_h);

    const int EB  = (EE + 255) / 256;
    const int KB  = (KEYS + 255) / 256;
    const int FT  = (NN + 127) / 128;       // 391 tiles of 128 nodes

    // CSR build interleaved; k_feat_mma kept at launch index 4 (ncu slot)
    k_zero <<<KB, 256>>>();
    k_count<<<EB, 256>>>(ei, ew);
    k_scan1<<<SCAN_NBLK, SCAN_B>>>();
    k_feat_mma<<<dim3(FT, RR), 256>>>(x, gW, gas, gad);        // layer 0
    k_scan2<<<1, 256>>>();
    k_scan3<<<KB, 256>>>();
    k_split<<<(LL * 9 * 64 * 32 + LL * 64 * 32 + 255) / 256, 256>>>(W1, W2);
    k_fill <<<EB, 256>>>(ei, ew);

    // layer 0 tail
    k_gat<<<(KEYS + 7) / 8, 256>>>(gb);
    k_mlp_mma<<<FT, 256>>>(x, 0, b1, b2, lng, lnb, hptr);

    // layer 1
    k_feat_mma<<<dim3(FT, RR), 256>>>(hptr, gW + RR * 64 * 128,
                                      gas + RR * HH * CC, gad + RR * HH * CC);
    k_gat<<<(KEYS + 7) / 8, 256>>>(gb + RR * HCC);
    k_mlp_mma<<<FT, 256>>>(hptr, 1, b1 + 64, b2 + 64,
                           lng + 64, lnb + 64, out);
}

// round 8
// speedup vs baseline: 1.9329x; 1.1362x over previous
#include <cuda_runtime.h>
#include <cuda_bf16.h>
#include <math.h>

#define NN 50000
#define EE 400000
#define RR 4
#define HH 2
#define CC 64
#define HCC 128   // H*C
#define RHC 512   // R*H*C
#define LL 2
#define LN_EPS 1e-5f
#define SLOPE 0.2f

#define KEYS (NN * RR)          // 200000 (node, relation) segments
#define SCAN_B 1024
#define SCAN_NBLK ((KEYS + SCAN_B - 1) / SCAN_B)   // 196

// ---------------- scratch (device globals; no allocations allowed) ----------
__device__ float g_feat[NN * RHC];   // [n][r*128 + h*64 + c]
__device__ float g_agg [NN * RHC];   // GAT outputs (post softmax-agg + bias)
__device__ float g_es  [NN * 8];     // [n][r*2+h]
__device__ float g_ed  [NN * 8];
__device__ float g_h   [NN * 64];    // hidden state between layers
// CSR (built once per call; graph identical across layers)
__device__ int   g_cnt[KEYS];
__device__ int   g_off[KEYS];
__device__ int   g_cur[KEYS];
__device__ int   g_bsum[SCAN_NBLK];
__device__ int   g_src[2 * EE];
// pre-split weights in MMA-fragment uint4 layout {bh0,bh1,bl0,bl1}
__device__ uint4 g_wgf[LL * RR * 128 * 16];   // GAT W: [(l,r)][n(128)][ks(4)*q(4)]
__device__ uint4 g_w1f[LL * 9 * 64 * 16];     // MLP W1: [(l,ch)][n(64)][16]
__device__ uint4 g_w2f[LL * 64 * 16];         // MLP W2: [l][n(64)][16]

__device__ __forceinline__ float lrelu(float x) { return x > 0.f ? x : SLOPE * x; }

__device__ __forceinline__ void split2(float2 v, unsigned& hi, unsigned& lo)
{
    __nv_bfloat162 h = __floats2bfloat162_rn(v.x, v.y);
    float2 hf = __bfloat1622float2(h);
    __nv_bfloat162 l = __floats2bfloat162_rn(v.x - hf.x, v.y - hf.y);
    hi = *(unsigned*)&h;
    lo = *(unsigned*)&l;
}

__device__ __forceinline__ void mma16816(float* c, const unsigned* a,
                                         unsigned b0, unsigned b1)
{
    asm volatile(
        "mma.sync.aligned.m16n8k16.row.col.f32.bf16.bf16.f32 "
        "{%0,%1,%2,%3}, {%4,%5,%6,%7}, {%8,%9}, {%0,%1,%2,%3};"
        : "+f"(c[0]), "+f"(c[1]), "+f"(c[2]), "+f"(c[3])
        : "r"(a[0]), "r"(a[1]), "r"(a[2]), "r"(a[3]), "r"(b0), "r"(b1));
}

// issue all 3 split-MMAs for one fragment pack
__device__ __forceinline__ void mma_pack(float* c, const unsigned* ahi,
                                         const unsigned* alo, uint4 f)
{
    mma16816(c, ahi, f.x, f.y);   // hi*hi
    mma16816(c, ahi, f.z, f.w);   // hi*lo
    mma16816(c, alo, f.x, f.y);   // lo*hi
}

// ================= weight pre-split (fragment layout) ========================
// GAT W: for (l,r,n,ks,q): bh0 = bf16x2(W[k0][n],W[k0+1][n]), k0=ks*16+q*2;
//                          bh1 at k0+8; bl* = residuals.
__global__ void k_split_gat(const float* __restrict__ W)
{
    int i = blockIdx.x * blockDim.x + threadIdx.x;
    if (i >= LL * RR * 128 * 16) return;
    int q  = i & 3;
    int ks = (i >> 2) & 3;
    int n  = (i >> 4) & 127;
    int lr = i >> 11;                       // l*4 + r
    const float* Wb = W + lr * 64 * 128;    // [k][n]
    int k0 = ks * 16 + q * 2;
    unsigned h0, l0, h1, l1;
    split2(make_float2(Wb[k0 * 128 + n],       Wb[(k0 + 1) * 128 + n]), h0, l0);
    split2(make_float2(Wb[(k0 + 8) * 128 + n], Wb[(k0 + 9) * 128 + n]), h1, l1);
    g_wgf[(lr * 128 + n) * 16 + ks * 4 + q] = make_uint4(h0, h1, l0, l1);
}

__global__ void k_split_mlp(const float* __restrict__ W1, const float* __restrict__ W2)
{
    int i = blockIdx.x * blockDim.x + threadIdx.x;
    if (i < LL * 9 * 64 * 16) {
        int q  = i & 3;
        int ks = (i >> 2) & 3;
        int n  = (i >> 4) & 63;
        int ch = (i >> 10) % 9;
        int l  = i / (9 * 1024);
        const float* Wb = W1 + l * 576 * 64;         // [k][n], n stride 64
        int k0 = ch * 64 + ks * 16 + q * 2;
        unsigned h0, l0, h1, l1;
        split2(make_float2(Wb[k0 * 64 + n],       Wb[(k0 + 1) * 64 + n]), h0, l0);
        split2(make_float2(Wb[(k0 + 8) * 64 + n], Wb[(k0 + 9) * 64 + n]), h1, l1);
        g_w1f[((l * 9 + ch) * 64 + n) * 16 + ks * 4 + q] = make_uint4(h0, h1, l0, l1);
    } else if (i < LL * 9 * 64 * 16 + LL * 64 * 16) {
        int i2 = i - LL * 9 * 64 * 16;
        int q  = i2 & 3;
        int ks = (i2 >> 2) & 3;
        int n  = (i2 >> 4) & 63;
        int l  = i2 >> 10;
        const float* Wb = W2 + l * 64 * 64;
        int k0 = ks * 16 + q * 2;
        unsigned h0, l0, h1, l1;
        split2(make_float2(Wb[k0 * 64 + n],       Wb[(k0 + 1) * 64 + n]), h0, l0);
        split2(make_float2(Wb[(k0 + 8) * 64 + n], Wb[(k0 + 9) * 64 + n]), h1, l1);
        g_w2f[(l * 64 + n) * 16 + ks * 4 + q] = make_uint4(h0, h1, l0, l1);
    }
}

// ================= CSR build =================================================
__global__ void k_zero()
{
    int i = blockIdx.x * blockDim.x + threadIdx.x;
    if (i < KEYS) g_cnt[i] = 0;
}

__global__ void k_count(const int* __restrict__ ei, const float* __restrict__ ew)
{
    int e = blockIdx.x * blockDim.x + threadIdx.x;
    if (e >= EE) return;
    int s = ei[e], d = ei[EE + e];
    float w = ew[e];
    if (w == 0.f) return;
    int r0 = (w > 0.f) ? 0 : 2;
    atomicAdd(&g_cnt[d * 4 + r0], 1);
    atomicAdd(&g_cnt[s * 4 + r0 + 1], 1);
}

__global__ void k_scan1()
{
    __shared__ int sh[SCAN_B];
    int tid = threadIdx.x;
    int i = blockIdx.x * SCAN_B + tid;
    int v = (i < KEYS) ? g_cnt[i] : 0;
    sh[tid] = v;
    __syncthreads();
    #pragma unroll
    for (int off = 1; off < SCAN_B; off <<= 1) {
        int t = (tid >= off) ? sh[tid - off] : 0;
        __syncthreads();
        sh[tid] += t;
        __syncthreads();
    }
    if (i < KEYS) g_off[i] = sh[tid] - v;
    if (tid == SCAN_B - 1) g_bsum[blockIdx.x] = sh[tid];
}

__global__ void k_scan2()
{
    __shared__ int sh[256];
    int t = threadIdx.x;
    int v = (t < SCAN_NBLK) ? g_bsum[t] : 0;
    sh[t] = v;
    __syncthreads();
    #pragma unroll
    for (int off = 1; off < 256; off <<= 1) {
        int x = (t >= off) ? sh[t - off] : 0;
        __syncthreads();
        sh[t] += x;
        __syncthreads();
    }
    if (t < SCAN_NBLK) g_bsum[t] = sh[t] - v;
}

__global__ void k_scan3()
{
    int i = blockIdx.x * blockDim.x + threadIdx.x;
    if (i >= KEYS) return;
    int o = g_off[i] + g_bsum[i >> 10];
    g_off[i] = o;
    g_cur[i] = o;
}

__global__ void k_fill(const int* __restrict__ ei, const float* __restrict__ ew)
{
    int e = blockIdx.x * blockDim.x + threadIdx.x;
    if (e >= EE) return;
    int s = ei[e], d = ei[EE + e];
    float w = ew[e];
    if (w == 0.f) return;
    int r0 = (w > 0.f) ? 0 : 2;
    int p1 = atomicAdd(&g_cur[d * 4 + r0], 1);
    g_src[p1] = s;
    int p2 = atomicAdd(&g_cur[s * 4 + r0 + 1], 1);
    g_src[p2] = d;
}

// ================= feat GEMM (bf16-split MMA, fragment-packed W) =============
// Block: 128 nodes x 128 cols (one relation). smem W stride 20 uint4/row
// (conflict-free per quarter-warp).
__global__ __launch_bounds__(256) void k_feat_mma(
    const float* __restrict__ hin, int l,
    const float* __restrict__ asrc, const float* __restrict__ adst)
{
    __shared__ uint4 sW[128 * 20];
    __shared__ float s_as[128], s_ad[128];

    const int tid = threadIdx.x;
    const int r   = blockIdx.y;
    const int nb  = blockIdx.x * 128;

    const uint4* wg = g_wgf + (l * RR + r) * 128 * 16;
    #pragma unroll
    for (int i = tid; i < 2048; i += 256) {
        sW[(i >> 4) * 20 + (i & 15)] = wg[i];
    }
    if (tid < 128) {
        s_as[tid] = asrc[r * 128 + tid];
        s_ad[tid] = adst[r * 128 + tid];
    }
    __syncthreads();

    const int w = tid >> 5, ln = tid & 31;
    const int g = ln >> 2, q = ln & 3;
    const int row0 = nb + w * 16 + g;

    float c[16][4];
    #pragma unroll
    for (int t = 0; t < 16; t++) {
        c[t][0] = 0.f; c[t][1] = 0.f; c[t][2] = 0.f; c[t][3] = 0.f;
    }

    const int ra = min(row0, NN - 1);
    const int rb = min(row0 + 8, NN - 1);

    #pragma unroll
    for (int ks = 0; ks < 4; ks++) {
        int c0 = ks * 16 + q * 2;
        float2 x00 = *(const float2*)(hin + ra * 64 + c0);
        float2 x10 = *(const float2*)(hin + rb * 64 + c0);
        float2 x01 = *(const float2*)(hin + ra * 64 + c0 + 8);
        float2 x11 = *(const float2*)(hin + rb * 64 + c0 + 8);
        unsigned ahi[4], alo[4];
        split2(x00, ahi[0], alo[0]);
        split2(x10, ahi[1], alo[1]);
        split2(x01, ahi[2], alo[2]);
        split2(x11, ahi[3], alo[3]);

        #pragma unroll
        for (int t = 0; t < 16; t++) {
            uint4 f = sW[(t * 8 + g) * 20 + ks * 4 + q];
            mma_pack(c[t], ahi, alo, f);
        }
    }

    const bool ok0 = row0 < NN, ok1 = (row0 + 8) < NN;
    float2* out2 = (float2*)g_feat;
    #pragma unroll
    for (int t = 0; t < 16; t++) {
        int colw = t * 4 + q;
        if (ok0) out2[row0 * 256 + r * 64 + colw] = make_float2(c[t][0], c[t][1]);
        if (ok1) out2[(row0 + 8) * 256 + r * 64 + colw] = make_float2(c[t][2], c[t][3]);
    }

    // fused attention scores
    float es00 = 0.f, es01 = 0.f, es10 = 0.f, es11 = 0.f;
    float ed00 = 0.f, ed01 = 0.f, ed10 = 0.f, ed11 = 0.f;
    #pragma unroll
    for (int t = 0; t < 16; t++) {
        int col = t * 8 + q * 2;
        float a0 = s_as[col], a1 = s_as[col + 1];
        float d0 = s_ad[col], d1 = s_ad[col + 1];
        if (t < 8) {
            es00 += c[t][0] * a0 + c[t][1] * a1;
            ed00 += c[t][0] * d0 + c[t][1] * d1;
            es10 += c[t][2] * a0 + c[t][3] * a1;
            ed10 += c[t][2] * d0 + c[t][3] * d1;
        } else {
            es01 += c[t][0] * a0 + c[t][1] * a1;
            ed01 += c[t][0] * d0 + c[t][1] * d1;
            es11 += c[t][2] * a0 + c[t][3] * a1;
            ed11 += c[t][2] * d0 + c[t][3] * d1;
        }
    }
    const unsigned FULL = 0xffffffffu;
    #pragma unroll
    for (int o = 1; o <= 2; o <<= 1) {
        es00 += __shfl_xor_sync(FULL, es00, o);
        es01 += __shfl_xor_sync(FULL, es01, o);
        es10 += __shfl_xor_sync(FULL, es10, o);
        es11 += __shfl_xor_sync(FULL, es11, o);
        ed00 += __shfl_xor_sync(FULL, ed00, o);
        ed01 += __shfl_xor_sync(FULL, ed01, o);
        ed10 += __shfl_xor_sync(FULL, ed10, o);
        ed11 += __shfl_xor_sync(FULL, ed11, o);
    }
    if (q == 0) {
        if (ok0) {
            g_es[row0 * 8 + r * 2 + 0] = es00;
            g_es[row0 * 8 + r * 2 + 1] = es01;
            g_ed[row0 * 8 + r * 2 + 0] = ed00;
            g_ed[row0 * 8 + r * 2 + 1] = ed01;
        }
        if (ok1) {
            g_es[(row0 + 8) * 8 + r * 2 + 0] = es10;
            g_es[(row0 + 8) * 8 + r * 2 + 1] = es11;
            g_ed[(row0 + 8) * 8 + r * 2 + 0] = ed10;
            g_ed[(row0 + 8) * 8 + r * 2 + 1] = ed11;
        }
    }
}

// ---------------- fused GAT softmax + aggregation (no atomics) --------------
__global__ void k_gat(const float* __restrict__ bias)
{
    const unsigned FULL = 0xffffffffu;
    int key = blockIdx.x * 8 + (threadIdx.x >> 5);
    if (key >= KEYS) return;
    int lane = threadIdx.x & 31;
    int n = key >> 2, r = key & 3;

    int beg = g_off[key];
    int num = g_cnt[key];

    float2 edv = ((const float2*)g_ed)[n * 4 + r];
    float2 esn = ((const float2*)g_es)[n * 4 + r];
    float self0 = lrelu(esn.x + edv.x);
    float self1 = lrelu(esn.y + edv.y);

    float m0 = self0, m1 = self1;
    for (int i = lane; i < num; i += 32) {
        int s = g_src[beg + i];
        float2 e2 = ((const float2*)g_es)[s * 4 + r];
        m0 = fmaxf(m0, lrelu(e2.x + edv.x));
        m1 = fmaxf(m1, lrelu(e2.y + edv.y));
    }
    #pragma unroll
    for (int o = 16; o; o >>= 1) {
        m0 = fmaxf(m0, __shfl_xor_sync(FULL, m0, o));
        m1 = fmaxf(m1, __shfl_xor_sync(FULL, m1, o));
    }

    float den0 = 0.f, den1 = 0.f;
    float4 acc = make_float4(0.f, 0.f, 0.f, 0.f);
    const float4* feat4 = (const float4*)g_feat;
    int col = r * 32 + lane;

    for (int base = 0; base < num; base += 32) {
        int cnt = min(32, num - base);
        int sj = 0;
        float ex = 0.f, ey = 0.f;
        if (lane < cnt) {
            sj = g_src[beg + base + lane];
            float2 e2 = ((const float2*)g_es)[sj * 4 + r];
            ex = e2.x; ey = e2.y;
        }
        for (int j = 0; j < cnt; j++) {
            int s    = __shfl_sync(FULL, sj, j);
            float jx = __shfl_sync(FULL, ex, j);
            float jy = __shfl_sync(FULL, ey, j);
            float p0 = __expf(lrelu(jx + edv.x) - m0);
            float p1 = __expf(lrelu(jy + edv.y) - m1);
            den0 += p0; den1 += p1;
            float pl = (lane < 16) ? p0 : p1;
            float4 f = feat4[s * 128 + col];
            acc.x += pl * f.x; acc.y += pl * f.y;
            acc.z += pl * f.z; acc.w += pl * f.w;
        }
    }
    {
        float p0 = __expf(self0 - m0);
        float p1 = __expf(self1 - m1);
        den0 += p0; den1 += p1;
        float pl = (lane < 16) ? p0 : p1;
        float4 f = feat4[n * 128 + col];
        acc.x += pl * f.x; acc.y += pl * f.y;
        acc.z += pl * f.z; acc.w += pl * f.w;
    }

    float inv = 1.f / ((lane < 16) ? den0 : den1);
    float4 b = ((const float4*)bias)[col];
    ((float4*)g_agg)[n * 128 + col] =
        make_float4(acc.x * inv + b.x, acc.y * inv + b.y,
                    acc.z * inv + b.z, acc.w * inv + b.w);
}

// ================= MLP via bf16-split MMA + fused residual/LN ================
__global__ __launch_bounds__(256) void k_mlp_mma(
    const float* __restrict__ hin, int l,
    const float* __restrict__ b1, const float* __restrict__ b2,
    const float* __restrict__ lng, const float* __restrict__ lnb,
    float* __restrict__ hout)
{
    __shared__ uint4 sW[64 * 20];
    __shared__ float s_b1[64], s_b2[64], s_lng[64], s_lnb[64];

    const int tid = threadIdx.x;
    const int w = tid >> 5, ln = tid & 31;
    const int g = ln >> 2, q = ln & 3;
    const int nb = blockIdx.x * 128;
    const int row0 = nb + w * 16 + g;
    const int ra = min(row0, NN - 1);
    const int rb = min(row0 + 8, NN - 1);

    if (tid < 64) {
        s_b1[tid]  = b1[tid];
        s_b2[tid]  = b2[tid];
        s_lng[tid] = lng[tid];
        s_lnb[tid] = lnb[tid];
    }

    float c1[8][4];
    #pragma unroll
    for (int t = 0; t < 8; t++) {
        c1[t][0] = 0.f; c1[t][1] = 0.f; c1[t][2] = 0.f; c1[t][3] = 0.f;
    }

    const uint4* w1f = g_w1f + l * 9 * 1024;

    for (int ch = 0; ch < 9; ch++) {
        __syncthreads();
        #pragma unroll
        for (int i = tid; i < 1024; i += 256) {
            sW[(i >> 4) * 20 + (i & 15)] = w1f[ch * 1024 + i];
        }
        __syncthreads();

        #pragma unroll
        for (int ks = 0; ks < 4; ks++) {
            float2 x00, x10, x01, x11;
            if (ch == 0) {
                int c0 = ks * 16 + q * 2;
                x00 = *(const float2*)(hin + ra * 64 + c0);
                x10 = *(const float2*)(hin + rb * 64 + c0);
                x01 = *(const float2*)(hin + ra * 64 + c0 + 8);
                x11 = *(const float2*)(hin + rb * 64 + c0 + 8);
            } else {
                int c0 = (ch - 1) * 64 + ks * 16 + q * 2;
                x00 = *(const float2*)(g_agg + ra * 512 + c0);
                x10 = *(const float2*)(g_agg + rb * 512 + c0);
                x01 = *(const float2*)(g_agg + ra * 512 + c0 + 8);
                x11 = *(const float2*)(g_agg + rb * 512 + c0 + 8);
            }
            unsigned ahi[4], alo[4];
            split2(x00, ahi[0], alo[0]);
            split2(x10, ahi[1], alo[1]);
            split2(x01, ahi[2], alo[2]);
            split2(x11, ahi[3], alo[3]);

            #pragma unroll
            for (int t = 0; t < 8; t++) {
                uint4 f = sW[(t * 8 + g) * 20 + ks * 4 + q];
                mma_pack(c1[t], ahi, alo, f);
            }
        }
    }

    // ---- tanh + bias -> A fragments for GEMM2 ----
    unsigned ahi2[4][4], alo2[4][4];
    #pragma unroll
    for (int t = 0; t < 8; t++) {
        int col0 = t * 8 + q * 2;
        float z0 = tanhf(c1[t][0] + s_b1[col0]);
        float z1 = tanhf(c1[t][1] + s_b1[col0 + 1]);
        float z2 = tanhf(c1[t][2] + s_b1[col0]);
        float z3 = tanhf(c1[t][3] + s_b1[col0 + 1]);
        int kt = t >> 1;
        int o = (t & 1) ? 2 : 0;
        split2(make_float2(z0, z1), ahi2[kt][o + 0], alo2[kt][o + 0]);
        split2(make_float2(z2, z3), ahi2[kt][o + 1], alo2[kt][o + 1]);
    }

    __syncthreads();
    #pragma unroll
    for (int i = tid; i < 1024; i += 256) {
        sW[(i >> 4) * 20 + (i & 15)] = g_w2f[l * 1024 + i];
    }
    __syncthreads();

    float c2[8][4];
    #pragma unroll
    for (int t = 0; t < 8; t++) {
        c2[t][0] = 0.f; c2[t][1] = 0.f; c2[t][2] = 0.f; c2[t][3] = 0.f;
    }
    #pragma unroll
    for (int kt = 0; kt < 4; kt++) {
        #pragma unroll
        for (int t = 0; t < 8; t++) {
            uint4 f = sW[(t * 8 + g) * 20 + kt * 4 + q];
            mma_pack(c2[t], ahi2[kt], alo2[kt], f);
        }
    }

    // ---- +b2 +residual, LayerNorm, store ----
    float v[8][4];
    float sA = 0.f, qA = 0.f, sB = 0.f, qB = 0.f;
    #pragma unroll
    for (int t = 0; t < 8; t++) {
        int col0 = t * 8 + q * 2;
        float2 r0 = *(const float2*)(hin + ra * 64 + col0);
        float2 r1 = *(const float2*)(hin + rb * 64 + col0);
        v[t][0] = c2[t][0] + s_b2[col0]     + r0.x;
        v[t][1] = c2[t][1] + s_b2[col0 + 1] + r0.y;
        v[t][2] = c2[t][2] + s_b2[col0]     + r1.x;
        v[t][3] = c2[t][3] + s_b2[col0 + 1] + r1.y;
        sA += v[t][0] + v[t][1];
        qA += v[t][0] * v[t][0] + v[t][1] * v[t][1];
        sB += v[t][2] + v[t][3];
        qB += v[t][2] * v[t][2] + v[t][3] * v[t][3];
    }
    const unsigned FULL = 0xffffffffu;
    #pragma unroll
    for (int o = 1; o <= 2; o <<= 1) {
        sA += __shfl_xor_sync(FULL, sA, o);
        qA += __shfl_xor_sync(FULL, qA, o);
        sB += __shfl_xor_sync(FULL, sB, o);
        qB += __shfl_xor_sync(FULL, qB, o);
    }
    float muA = sA * (1.f / 64.f);
    float rsA = rsqrtf(qA * (1.f / 64.f) - muA * muA + LN_EPS);
    float muB = sB * (1.f / 64.f);
    float rsB = rsqrtf(qB * (1.f / 64.f) - muB * muB + LN_EPS);

    const bool ok0 = row0 < NN, ok1 = (row0 + 8) < NN;
    #pragma unroll
    for (int t = 0; t < 8; t++) {
        int col0 = t * 8 + q * 2;
        float g0 = s_lng[col0], g1 = s_lng[col0 + 1];
        float o0 = s_lnb[col0], o1 = s_lnb[col0 + 1];
        if (ok0)
            *(float2*)(hout + row0 * 64 + col0) =
                make_float2((v[t][0] - muA) * rsA * g0 + o0,
                            (v[t][1] - muA) * rsA * g1 + o1);
        if (ok1)
            *(float2*)(hout + (row0 + 8) * 64 + col0) =
                make_float2((v[t][2] - muB) * rsB * g0 + o0,
                            (v[t][3] - muB) * rsB * g1 + o1);
    }
}

// ---------------- launch -----------------------------------------------------
extern "C" void kernel_launch(void* const* d_in, const int* in_sizes, int n_in,
                              void* d_out, int out_size)
{
    const float* x   = (const float*)d_in[0];
    const int*   ei  = (const int*)  d_in[1];
    const float* ew  = (const float*)d_in[2];
    const float* gW  = (const float*)d_in[3];
    const float* gas = (const float*)d_in[4];
    const float* gad = (const float*)d_in[5];
    const float* gb  = (const float*)d_in[6];
    const float* W1  = (const float*)d_in[7];
    const float* b1  = (const float*)d_in[8];
    const float* W2  = (const float*)d_in[9];
    const float* b2  = (const float*)d_in[10];
    const float* lng = (const float*)d_in[11];
    const float* lnb = (const float*)d_in[12];
    float* out = (float*)d_out;

    float* hptr = nullptr;
    cudaGetSymbolAddress((void**)&hptr, g_h);

    const int EB  = (EE + 255) / 256;
    const int KB  = (KEYS + 255) / 256;
    const int FT  = (NN + 127) / 128;       // 391 tiles of 128 nodes

    // k_feat_mma kept at launch index 3 (ncu capture slot)
    k_split_gat<<<(LL * RR * 128 * 16 + 255) / 256, 256>>>(gW);
    k_zero <<<KB, 256>>>();
    k_count<<<EB, 256>>>(ei, ew);
    k_feat_mma<<<dim3(FT, RR), 256>>>(x, 0, gas, gad);          // layer 0
    k_scan1<<<SCAN_NBLK, SCAN_B>>>();
    k_scan2<<<1, 256>>>();
    k_scan3<<<KB, 256>>>();
    k_split_mlp<<<(LL * 9 * 64 * 16 + LL * 64 * 16 + 255) / 256, 256>>>(W1, W2);
    k_fill <<<EB, 256>>>(ei, ew);

    // layer 0 tail
    k_gat<<<(KEYS + 7) / 8, 256>>>(gb);
    k_mlp_mma<<<FT, 256>>>(x, 0, b1, b2, lng, lnb, hptr);

    // layer 1
    k_feat_mma<<<dim3(FT, RR), 256>>>(hptr, 1,
                                      gas + RR * HH * CC, gad + RR * HH * CC);
    k_gat<<<(KEYS + 7) / 8, 256>>>(gb + RR * HCC);
    k_mlp_mma<<<FT, 256>>>(hptr, 1, b1 + 64, b2 + 64,
                           lng + 64, lnb + 64, out);
}

// round 10
// speedup vs baseline: 2.2100x; 1.1434x over previous
#include <cuda_runtime.h>
#include <cuda_bf16.h>
#include <math.h>

#define NN 50000
#define EE 400000
#define RR 4
#define HH 2
#define CC 64
#define HCC 128   // H*C
#define RHC 512   // R*H*C
#define LL 2
#define LN_EPS 1e-5f
#define SLOPE 0.2f

#define KEYS (NN * RR)          // 200000 (node, relation) segments
#define SCAN_B 1024
#define SCAN_NBLK ((KEYS + SCAN_B - 1) / SCAN_B)   // 196

// ---------------- scratch (device globals; no allocations allowed) ----------
__device__ float g_feat[NN * RHC];   // [n][r*128 + h*64 + c]
__device__ float g_agg [NN * RHC];   // GAT outputs (post softmax-agg + bias)
__device__ float g_es  [NN * 8];     // [n][r*2+h]
__device__ float g_ed  [NN * 8];
__device__ float g_h   [NN * 64];    // hidden state between layers
// CSR (built once per call; graph identical across layers)
__device__ int   g_cnt[KEYS];
__device__ int   g_off[KEYS];
__device__ int   g_cur[KEYS];
__device__ int   g_bsum[SCAN_NBLK];
__device__ int   g_src[2 * EE];
// pre-split weights in MMA-fragment uint4 layout {bh0,bh1,bl0,bl1}
__device__ uint4 g_wgf[LL * RR * 128 * 16];   // GAT W: [(l,r)][n(128)][ks(4)*q(4)]
__device__ uint4 g_w1f[LL * 9 * 64 * 16];     // MLP W1: [(l,ch)][n(64)][16]
__device__ uint4 g_w2f[LL * 64 * 16];         // MLP W2: [l][n(64)][16]

__device__ __forceinline__ float lrelu(float x) { return x > 0.f ? x : SLOPE * x; }

__device__ __forceinline__ void split2(float2 v, unsigned& hi, unsigned& lo)
{
    __nv_bfloat162 h = __floats2bfloat162_rn(v.x, v.y);
    float2 hf = __bfloat1622float2(h);
    __nv_bfloat162 l = __floats2bfloat162_rn(v.x - hf.x, v.y - hf.y);
    hi = *(unsigned*)&h;
    lo = *(unsigned*)&l;
}

__device__ __forceinline__ void mma16816(float* c, const unsigned* a,
                                         unsigned b0, unsigned b1)
{
    asm volatile(
        "mma.sync.aligned.m16n8k16.row.col.f32.bf16.bf16.f32 "
        "{%0,%1,%2,%3}, {%4,%5,%6,%7}, {%8,%9}, {%0,%1,%2,%3};"
        : "+f"(c[0]), "+f"(c[1]), "+f"(c[2]), "+f"(c[3])
        : "r"(a[0]), "r"(a[1]), "r"(a[2]), "r"(a[3]), "r"(b0), "r"(b1));
}

__device__ __forceinline__ void mma_pack(float* c, const unsigned* ahi,
                                         const unsigned* alo, uint4 f)
{
    mma16816(c, ahi, f.x, f.y);   // hi*hi
    mma16816(c, ahi, f.z, f.w);   // hi*lo
    mma16816(c, alo, f.x, f.y);   // lo*hi
}

// ================= k_init: zero counts + pre-split all weights ===============
__global__ void k_init(const float* __restrict__ gW,
                       const float* __restrict__ W1, const float* __restrict__ W2)
{
    int i = blockIdx.x * blockDim.x + threadIdx.x;
    if (i < KEYS) g_cnt[i] = 0;

    if (i < LL * RR * 128 * 16) {          // GAT weight split
        int q  = i & 3;
        int ks = (i >> 2) & 3;
        int n  = (i >> 4) & 127;
        int lr = i >> 11;
        const float* Wb = gW + lr * 64 * 128;    // [k][n]
        int k0 = ks * 16 + q * 2;
        unsigned h0, l0, h1, l1;
        split2(make_float2(Wb[k0 * 128 + n],       Wb[(k0 + 1) * 128 + n]), h0, l0);
        split2(make_float2(Wb[(k0 + 8) * 128 + n], Wb[(k0 + 9) * 128 + n]), h1, l1);
        g_wgf[(lr * 128 + n) * 16 + ks * 4 + q] = make_uint4(h0, h1, l0, l1);
    }
    if (i < LL * 9 * 64 * 16) {            // MLP W1 split
        int q  = i & 3;
        int ks = (i >> 2) & 3;
        int n  = (i >> 4) & 63;
        int ch = (i >> 10) % 9;
        int l  = i / (9 * 1024);
        const float* Wb = W1 + l * 576 * 64;
        int k0 = ch * 64 + ks * 16 + q * 2;
        unsigned h0, l0, h1, l1;
        split2(make_float2(Wb[k0 * 64 + n],       Wb[(k0 + 1) * 64 + n]), h0, l0);
        split2(make_float2(Wb[(k0 + 8) * 64 + n], Wb[(k0 + 9) * 64 + n]), h1, l1);
        g_w1f[((l * 9 + ch) * 64 + n) * 16 + ks * 4 + q] = make_uint4(h0, h1, l0, l1);
    }
    if (i < LL * 64 * 16) {                // MLP W2 split
        int q  = i & 3;
        int ks = (i >> 2) & 3;
        int n  = (i >> 4) & 63;
        int l  = i >> 10;
        const float* Wb = W2 + l * 64 * 64;
        int k0 = ks * 16 + q * 2;
        unsigned h0, l0, h1, l1;
        split2(make_float2(Wb[k0 * 64 + n],       Wb[(k0 + 1) * 64 + n]), h0, l0);
        split2(make_float2(Wb[(k0 + 8) * 64 + n], Wb[(k0 + 9) * 64 + n]), h1, l1);
        g_w2f[(l * 64 + n) * 16 + ks * 4 + q] = make_uint4(h0, h1, l0, l1);
    }
}

// ================= CSR build =================================================
__global__ void k_count(const int* __restrict__ ei, const float* __restrict__ ew)
{
    int e = blockIdx.x * blockDim.x + threadIdx.x;
    if (e >= EE) return;
    int s = ei[e], d = ei[EE + e];
    float w = ew[e];
    if (w == 0.f) return;
    int r0 = (w > 0.f) ? 0 : 2;
    atomicAdd(&g_cnt[d * 4 + r0], 1);
    atomicAdd(&g_cnt[s * 4 + r0 + 1], 1);
}

__global__ void k_scan1()
{
    __shared__ int sh[SCAN_B];
    int tid = threadIdx.x;
    int i = blockIdx.x * SCAN_B + tid;
    int v = (i < KEYS) ? g_cnt[i] : 0;
    sh[tid] = v;
    __syncthreads();
    #pragma unroll
    for (int off = 1; off < SCAN_B; off <<= 1) {
        int t = (tid >= off) ? sh[tid - off] : 0;
        __syncthreads();
        sh[tid] += t;
        __syncthreads();
    }
    if (i < KEYS) g_off[i] = sh[tid] - v;
    if (tid == SCAN_B - 1) g_bsum[blockIdx.x] = sh[tid];
}

__global__ void k_scan2()
{
    __shared__ int sh[256];
    int t = threadIdx.x;
    int v = (t < SCAN_NBLK) ? g_bsum[t] : 0;
    sh[t] = v;
    __syncthreads();
    #pragma unroll
    for (int off = 1; off < 256; off <<= 1) {
        int x = (t >= off) ? sh[t - off] : 0;
        __syncthreads();
        sh[t] += x;
        __syncthreads();
    }
    if (t < SCAN_NBLK) g_bsum[t] = sh[t] - v;
}

__global__ void k_scan3()
{
    int i = blockIdx.x * blockDim.x + threadIdx.x;
    if (i >= KEYS) return;
    int o = g_off[i] + g_bsum[i >> 10];
    g_off[i] = o;
    g_cur[i] = o;
}

__global__ void k_fill(const int* __restrict__ ei, const float* __restrict__ ew)
{
    int e = blockIdx.x * blockDim.x + threadIdx.x;
    if (e >= EE) return;
    int s = ei[e], d = ei[EE + e];
    float w = ew[e];
    if (w == 0.f) return;
    int r0 = (w > 0.f) ? 0 : 2;
    int p1 = atomicAdd(&g_cur[d * 4 + r0], 1);
    g_src[p1] = s;
    int p2 = atomicAdd(&g_cur[s * 4 + r0 + 1], 1);
    g_src[p2] = d;
}

// ================= feat GEMM (bf16-split MMA, 2-half accumulators) ===========
// Block: 128 nodes x 128 cols (one relation), 8 warps. Cols done in two halves
// of 64 to halve live accumulators -> 3 blocks/SM.
__global__ __launch_bounds__(256, 3) void k_feat_mma(
    const float* __restrict__ hin, int l,
    const float* __restrict__ asrc, const float* __restrict__ adst)
{
    __shared__ uint4 sW[128 * 20];
    __shared__ float4 s_asad[64];      // {as[c],as[c+1],ad[c],ad[c+1]}, c=2j

    const int tid = threadIdx.x;
    const int r   = blockIdx.y;
    const int nb  = blockIdx.x * 128;

    const uint4* wg = g_wgf + (l * RR + r) * 128 * 16;
    #pragma unroll
    for (int i = tid; i < 2048; i += 256) {
        sW[(i >> 4) * 20 + (i & 15)] = wg[i];
    }
    if (tid < 64) {
        float2 a = ((const float2*)(asrc + r * 128))[tid];
        float2 d = ((const float2*)(adst + r * 128))[tid];
        s_asad[tid] = make_float4(a.x, a.y, d.x, d.y);
    }
    __syncthreads();

    const int w = tid >> 5, ln = tid & 31;
    const int g = ln >> 2, q = ln & 3;
    const int row0 = nb + w * 16 + g;
    const int ra = min(row0, NN - 1);
    const int rb = min(row0 + 8, NN - 1);
    const bool ok0 = row0 < NN, ok1 = (row0 + 8) < NN;
    float2* out2 = (float2*)g_feat;

    // es/ed accumulators: [row a/b][head = half]
    float esA[2] = {0.f, 0.f}, edA[2] = {0.f, 0.f};
    float esB[2] = {0.f, 0.f}, edB[2] = {0.f, 0.f};

    #pragma unroll
    for (int half = 0; half < 2; half++) {
        float c[8][4];
        #pragma unroll
        for (int t = 0; t < 8; t++) {
            c[t][0] = 0.f; c[t][1] = 0.f; c[t][2] = 0.f; c[t][3] = 0.f;
        }
        #pragma unroll
        for (int ks = 0; ks < 4; ks++) {
            int c0 = ks * 16 + q * 2;
            float2 x00 = *(const float2*)(hin + ra * 64 + c0);
            float2 x10 = *(const float2*)(hin + rb * 64 + c0);
            float2 x01 = *(const float2*)(hin + ra * 64 + c0 + 8);
            float2 x11 = *(const float2*)(hin + rb * 64 + c0 + 8);
            unsigned ahi[4], alo[4];
            split2(x00, ahi[0], alo[0]);
            split2(x10, ahi[1], alo[1]);
            split2(x01, ahi[2], alo[2]);
            split2(x11, ahi[3], alo[3]);
            #pragma unroll
            for (int tt = 0; tt < 8; tt++) {
                int t = half * 8 + tt;
                uint4 f = sW[(t * 8 + g) * 20 + ks * 4 + q];
                mma_pack(c[tt], ahi, alo, f);
            }
        }
        // store + partial scores for this half (cols half*64 .. +63, head=half)
        #pragma unroll
        for (int tt = 0; tt < 8; tt++) {
            int t = half * 8 + tt;
            int colw = t * 4 + q;
            if (ok0) out2[row0 * 256 + r * 64 + colw] = make_float2(c[tt][0], c[tt][1]);
            if (ok1) out2[(row0 + 8) * 256 + r * 64 + colw] = make_float2(c[tt][2], c[tt][3]);
            float4 aa = s_asad[t * 4 + q];
            esA[half] += c[tt][0] * aa.x + c[tt][1] * aa.y;
            edA[half] += c[tt][0] * aa.z + c[tt][1] * aa.w;
            esB[half] += c[tt][2] * aa.x + c[tt][3] * aa.y;
            edB[half] += c[tt][2] * aa.z + c[tt][3] * aa.w;
        }
    }

    const unsigned FULL = 0xffffffffu;
    #pragma unroll
    for (int o = 1; o <= 2; o <<= 1) {
        esA[0] += __shfl_xor_sync(FULL, esA[0], o);
        esA[1] += __shfl_xor_sync(FULL, esA[1], o);
        esB[0] += __shfl_xor_sync(FULL, esB[0], o);
        esB[1] += __shfl_xor_sync(FULL, esB[1], o);
        edA[0] += __shfl_xor_sync(FULL, edA[0], o);
        edA[1] += __shfl_xor_sync(FULL, edA[1], o);
        edB[0] += __shfl_xor_sync(FULL, edB[0], o);
        edB[1] += __shfl_xor_sync(FULL, edB[1], o);
    }
    if (q == 0) {
        if (ok0) {
            g_es[row0 * 8 + r * 2 + 0] = esA[0];
            g_es[row0 * 8 + r * 2 + 1] = esA[1];
            g_ed[row0 * 8 + r * 2 + 0] = edA[0];
            g_ed[row0 * 8 + r * 2 + 1] = edA[1];
        }
        if (ok1) {
            g_es[(row0 + 8) * 8 + r * 2 + 0] = esB[0];
            g_es[(row0 + 8) * 8 + r * 2 + 1] = esB[1];
            g_ed[(row0 + 8) * 8 + r * 2 + 0] = edB[0];
            g_ed[(row0 + 8) * 8 + r * 2 + 1] = edB[1];
        }
    }
}

// ---------------- fused GAT: single-pass online softmax + aggregation -------
__global__ void k_gat(const float* __restrict__ bias)
{
    const unsigned FULL = 0xffffffffu;
    int key = blockIdx.x * 8 + (threadIdx.x >> 5);
    if (key >= KEYS) return;
    int lane = threadIdx.x & 31;
    int n = key >> 2, r = key & 3;

    int beg = g_off[key];
    int num = g_cnt[key];

    float2 edv = ((const float2*)g_ed)[n * 4 + r];
    float2 esn = ((const float2*)g_es)[n * 4 + r];
    float self0 = lrelu(esn.x + edv.x);
    float self1 = lrelu(esn.y + edv.y);

    float m0 = self0, m1 = self1;
    float den0 = 0.f, den1 = 0.f;
    float4 acc = make_float4(0.f, 0.f, 0.f, 0.f);
    const float4* feat4 = (const float4*)g_feat;
    int col = r * 32 + lane;

    for (int base = 0; base < num; base += 32) {
        int cnt = min(32, num - base);
        int sj = 0;
        float ex = 0.f, ey = 0.f;
        if (lane < cnt) {
            sj = g_src[beg + base + lane];
            float2 e2 = ((const float2*)g_es)[sj * 4 + r];
            ex = e2.x; ey = e2.y;
        }
        for (int j = 0; j < cnt; j++) {
            int s    = __shfl_sync(FULL, sj, j);
            float jx = __shfl_sync(FULL, ex, j);
            float jy = __shfl_sync(FULL, ey, j);
            float e0 = lrelu(jx + edv.x);
            float e1 = lrelu(jy + edv.y);
            float4 f = feat4[s * 128 + col];
            if (e0 > m0 || e1 > m1) {           // warp-uniform rescale path
                float nm0 = fmaxf(m0, e0), nm1 = fmaxf(m1, e1);
                float c0 = __expf(m0 - nm0), c1 = __expf(m1 - nm1);
                float p0 = __expf(e0 - nm0), p1 = __expf(e1 - nm1);
                den0 = den0 * c0 + p0;
                den1 = den1 * c1 + p1;
                m0 = nm0; m1 = nm1;
                float cl = (lane < 16) ? c0 : c1;
                float pl = (lane < 16) ? p0 : p1;
                acc.x = acc.x * cl + pl * f.x;
                acc.y = acc.y * cl + pl * f.y;
                acc.z = acc.z * cl + pl * f.z;
                acc.w = acc.w * cl + pl * f.w;
            } else {
                float p0 = __expf(e0 - m0);
                float p1 = __expf(e1 - m1);
                den0 += p0; den1 += p1;
                float pl = (lane < 16) ? p0 : p1;
                acc.x += pl * f.x; acc.y += pl * f.y;
                acc.z += pl * f.z; acc.w += pl * f.w;
            }
        }
    }
    // self loop (self <= m always)
    {
        float p0 = __expf(self0 - m0);
        float p1 = __expf(self1 - m1);
        den0 += p0; den1 += p1;
        float pl = (lane < 16) ? p0 : p1;
        float4 f = feat4[n * 128 + col];
        acc.x += pl * f.x; acc.y += pl * f.y;
        acc.z += pl * f.z; acc.w += pl * f.w;
    }

    float inv = 1.f / ((lane < 16) ? den0 : den1);
    float4 b = ((const float4*)bias)[col];
    ((float4*)g_agg)[n * 128 + col] =
        make_float4(acc.x * inv + b.x, acc.y * inv + b.y,
                    acc.z * inv + b.z, acc.w * inv + b.w);
}

// ================= MLP via bf16-split MMA + fused residual/LN ================
__global__ __launch_bounds__(256, 3) void k_mlp_mma(
    const float* __restrict__ hin, int l,
    const float* __restrict__ b1, const float* __restrict__ b2,
    const float* __restrict__ lng, const float* __restrict__ lnb,
    float* __restrict__ hout)
{
    __shared__ uint4 sW[64 * 20];
    __shared__ float2 s_b1[32];        // {b1[c], b1[c+1]}
    __shared__ float4 s_bg[32];        // {b2[c], b2[c+1], lng[c], lng[c+1]}
    __shared__ float2 s_lb[32];        // {lnb[c], lnb[c+1]}

    const int tid = threadIdx.x;
    const int w = tid >> 5, ln = tid & 31;
    const int g = ln >> 2, q = ln & 3;
    const int nb = blockIdx.x * 128;
    const int row0 = nb + w * 16 + g;
    const int ra = min(row0, NN - 1);
    const int rb = min(row0 + 8, NN - 1);

    if (tid < 32) {
        s_b1[tid] = ((const float2*)b1)[tid];
        float2 bb = ((const float2*)b2)[tid];
        float2 gg = ((const float2*)lng)[tid];
        s_bg[tid] = make_float4(bb.x, bb.y, gg.x, gg.y);
        s_lb[tid] = ((const float2*)lnb)[tid];
    }

    float c1[8][4];
    #pragma unroll
    for (int t = 0; t < 8; t++) {
        c1[t][0] = 0.f; c1[t][1] = 0.f; c1[t][2] = 0.f; c1[t][3] = 0.f;
    }

    const uint4* w1f = g_w1f + l * 9 * 1024;

    for (int ch = 0; ch < 9; ch++) {
        __syncthreads();
        #pragma unroll
        for (int i = tid; i < 1024; i += 256) {
            sW[(i >> 4) * 20 + (i & 15)] = w1f[ch * 1024 + i];
        }
        __syncthreads();

        #pragma unroll
        for (int ks = 0; ks < 4; ks++) {
            float2 x00, x10, x01, x11;
            if (ch == 0) {
                int c0 = ks * 16 + q * 2;
                x00 = *(const float2*)(hin + ra * 64 + c0);
                x10 = *(const float2*)(hin + rb * 64 + c0);
                x01 = *(const float2*)(hin + ra * 64 + c0 + 8);
                x11 = *(const float2*)(hin + rb * 64 + c0 + 8);
            } else {
                int c0 = (ch - 1) * 64 + ks * 16 + q * 2;
                x00 = *(const float2*)(g_agg + ra * 512 + c0);
                x10 = *(const float2*)(g_agg + rb * 512 + c0);
                x01 = *(const float2*)(g_agg + ra * 512 + c0 + 8);
                x11 = *(const float2*)(g_agg + rb * 512 + c0 + 8);
            }
            unsigned ahi[4], alo[4];
            split2(x00, ahi[0], alo[0]);
            split2(x10, ahi[1], alo[1]);
            split2(x01, ahi[2], alo[2]);
            split2(x11, ahi[3], alo[3]);

            #pragma unroll
            for (int t = 0; t < 8; t++) {
                uint4 f = sW[(t * 8 + g) * 20 + ks * 4 + q];
                mma_pack(c1[t], ahi, alo, f);
            }
        }
    }

    // ---- tanh + bias -> A fragments for GEMM2 ----
    unsigned ahi2[4][4], alo2[4][4];
    #pragma unroll
    for (int t = 0; t < 8; t++) {
        float2 bj = s_b1[t * 4 + q];
        float z0 = tanhf(c1[t][0] + bj.x);
        float z1 = tanhf(c1[t][1] + bj.y);
        float z2 = tanhf(c1[t][2] + bj.x);
        float z3 = tanhf(c1[t][3] + bj.y);
        int kt = t >> 1;
        int o = (t & 1) ? 2 : 0;
        split2(make_float2(z0, z1), ahi2[kt][o + 0], alo2[kt][o + 0]);
        split2(make_float2(z2, z3), ahi2[kt][o + 1], alo2[kt][o + 1]);
    }

    __syncthreads();
    #pragma unroll
    for (int i = tid; i < 1024; i += 256) {
        sW[(i >> 4) * 20 + (i & 15)] = g_w2f[l * 1024 + i];
    }
    __syncthreads();

    float c2[8][4];
    #pragma unroll
    for (int t = 0; t < 8; t++) {
        c2[t][0] = 0.f; c2[t][1] = 0.f; c2[t][2] = 0.f; c2[t][3] = 0.f;
    }
    #pragma unroll
    for (int kt = 0; kt < 4; kt++) {
        #pragma unroll
        for (int t = 0; t < 8; t++) {
            uint4 f = sW[(t * 8 + g) * 20 + kt * 4 + q];
            mma_pack(c2[t], ahi2[kt], alo2[kt], f);
        }
    }

    // ---- +b2 +residual (in place), LayerNorm sums ----
    float sA = 0.f, qA = 0.f, sB = 0.f, qB = 0.f;
    #pragma unroll
    for (int t = 0; t < 8; t++) {
        int col0 = t * 8 + q * 2;
        float4 bg = s_bg[t * 4 + q];
        float2 r0 = *(const float2*)(hin + ra * 64 + col0);
        float2 r1 = *(const float2*)(hin + rb * 64 + col0);
        c2[t][0] += bg.x + r0.x;
        c2[t][1] += bg.y + r0.y;
        c2[t][2] += bg.x + r1.x;
        c2[t][3] += bg.y + r1.y;
        sA += c2[t][0] + c2[t][1];
        qA += c2[t][0] * c2[t][0] + c2[t][1] * c2[t][1];
        sB += c2[t][2] + c2[t][3];
        qB += c2[t][2] * c2[t][2] + c2[t][3] * c2[t][3];
    }
    const unsigned FULL = 0xffffffffu;
    #pragma unroll
    for (int o = 1; o <= 2; o <<= 1) {
        sA += __shfl_xor_sync(FULL, sA, o);
        qA += __shfl_xor_sync(FULL, qA, o);
        sB += __shfl_xor_sync(FULL, sB, o);
        qB += __shfl_xor_sync(FULL, qB, o);
    }
    float muA = sA * (1.f / 64.f);
    float rsA = rsqrtf(qA * (1.f / 64.f) - muA * muA + LN_EPS);
    float muB = sB * (1.f / 64.f);
    float rsB = rsqrtf(qB * (1.f / 64.f) - muB * muB + LN_EPS);

    const bool ok0 = row0 < NN, ok1 = (row0 + 8) < NN;
    #pragma unroll
    for (int t = 0; t < 8; t++) {
        int col0 = t * 8 + q * 2;
        float4 bg = s_bg[t * 4 + q];
        float2 ob = s_lb[t * 4 + q];
        if (ok0)
            *(float2*)(hout + row0 * 64 + col0) =
                make_float2((c2[t][0] - muA) * rsA * bg.z + ob.x,
                            (c2[t][1] - muA) * rsA * bg.w + ob.y);
        if (ok1)
            *(float2*)(hout + (row0 + 8) * 64 + col0) =
                make_float2((c2[t][2] - muB) * rsB * bg.z + ob.x,
                            (c2[t][3] - muB) * rsB * bg.w + ob.y);
    }
}

// ---------------- launch -----------------------------------------------------
extern "C" void kernel_launch(void* const* d_in, const int* in_sizes, int n_in,
                              void* d_out, int out_size)
{
    const float* x   = (const float*)d_in[0];
    const int*   ei  = (const int*)  d_in[1];
    const float* ew  = (const float*)d_in[2];
    const float* gW  = (const float*)d_in[3];
    const float* gas = (const float*)d_in[4];
    const float* gad = (const float*)d_in[5];
    const float* gb  = (const float*)d_in[6];
    const float* W1  = (const float*)d_in[7];
    const float* b1  = (const float*)d_in[8];
    const float* W2  = (const float*)d_in[9];
    const float* b2  = (const float*)d_in[10];
    const float* lng = (const float*)d_in[11];
    const float* lnb = (const float*)d_in[12];
    float* out = (float*)d_out;

    float* hptr = nullptr;
    cudaGetSymbolAddress((void**)&hptr, g_h);

    const int EB  = (EE + 255) / 256;
    const int KB  = (KEYS + 255) / 256;
    const int FT  = (NN + 127) / 128;       // 391 tiles of 128 nodes

    // k_feat_mma at launch index 3 (ncu capture slot)
    k_init <<<KB, 256>>>(gW, W1, W2);
    k_count<<<EB, 256>>>(ei, ew);
    k_scan1<<<SCAN_NBLK, SCAN_B>>>();
    k_feat_mma<<<dim3(FT, RR), 256>>>(x, 0, gas, gad);          // layer 0
    k_scan2<<<1, 256>>>();
    k_scan3<<<KB, 256>>>();
    k_fill <<<EB, 256>>>(ei, ew);

    // layer 0 tail
    k_gat<<<(KEYS + 7) / 8, 256>>>(gb);
    k_mlp_mma<<<FT, 256>>>(x, 0, b1, b2, lng, lnb, hptr);

    // layer 1
    k_feat_mma<<<dim3(FT, RR), 256>>>(hptr, 1,
                                      gas + RR * HH * CC, gad + RR * HH * CC);
    k_gat<<<(KEYS + 7) / 8, 256>>>(gb + RR * HCC);
    k_mlp_mma<<<FT, 256>>>(hptr, 1, b1 + 64, b2 + 64,
                           lng + 64, lnb + 64, out);
}

// round 12
// speedup vs baseline: 2.3595x; 1.0676x over previous
#include <cuda_runtime.h>
#include <cuda_bf16.h>
#include <math.h>

#define NN 50000
#define EE 400000
#define RR 4
#define HH 2
#define CC 64
#define HCC 128   // H*C
#define RHC 512   // R*H*C
#define LL 2
#define LN_EPS 1e-5f
#define SLOPE 0.2f

#define KEYS (NN * RR)          // 200000; key = r*NN + n (relation-major)
#define SCAN_B 1024
#define SCAN_NBLK ((KEYS + SCAN_B - 1) / SCAN_B)   // 196

// ---------------- scratch (device globals; no allocations allowed) ----------
__device__ float g_feat[NN * RHC];   // RELATION-MAJOR: [r][n][h*64+c]
__device__ float g_agg [NN * RHC];   // node-major: [n][r*128 + h*64 + c]
__device__ float g_es  [NN * 8];     // [r][n][h] as float2 pairs
__device__ float g_ed  [NN * 8];
__device__ float g_h   [NN * 64];    // hidden state between layers
// CSR (built once per call; graph identical across layers)
__device__ int   g_cnt[KEYS];
__device__ int   g_off[KEYS];
__device__ int   g_cur[KEYS];
__device__ int   g_bsum[SCAN_NBLK];
__device__ int   g_src[2 * EE];
// pre-split weights in MMA-fragment uint4 layout {bh0,bh1,bl0,bl1}
__device__ uint4 g_wgf[LL * RR * 128 * 16];   // GAT W: [(l,r)][n(128)][ks(4)*q(4)]
__device__ uint4 g_w1f[LL * 9 * 64 * 16];     // MLP W1: [(l,ch)][n(64)][16]
__device__ uint4 g_w2f[LL * 64 * 16];         // MLP W2: [l][n(64)][16]

__device__ __forceinline__ float lrelu(float x) { return x > 0.f ? x : SLOPE * x; }

__device__ __forceinline__ void split2(float2 v, unsigned& hi, unsigned& lo)
{
    __nv_bfloat162 h = __floats2bfloat162_rn(v.x, v.y);
    float2 hf = __bfloat1622float2(h);
    __nv_bfloat162 l = __floats2bfloat162_rn(v.x - hf.x, v.y - hf.y);
    hi = *(unsigned*)&h;
    lo = *(unsigned*)&l;
}

__device__ __forceinline__ void mma16816(float* c, const unsigned* a,
                                         unsigned b0, unsigned b1)
{
    asm volatile(
        "mma.sync.aligned.m16n8k16.row.col.f32.bf16.bf16.f32 "
        "{%0,%1,%2,%3}, {%4,%5,%6,%7}, {%8,%9}, {%0,%1,%2,%3};"
        : "+f"(c[0]), "+f"(c[1]), "+f"(c[2]), "+f"(c[3])
        : "r"(a[0]), "r"(a[1]), "r"(a[2]), "r"(a[3]), "r"(b0), "r"(b1));
}

__device__ __forceinline__ void mma_pack(float* c, const unsigned* ahi,
                                         const unsigned* alo, uint4 f)
{
    mma16816(c, ahi, f.x, f.y);   // hi*hi
    mma16816(c, ahi, f.z, f.w);   // hi*lo
    mma16816(c, alo, f.x, f.y);   // lo*hi
}

// ================= k_init: zero counts + pre-split all weights ===============
__global__ void k_init(const float* __restrict__ gW,
                       const float* __restrict__ W1, const float* __restrict__ W2)
{
    int i = blockIdx.x * blockDim.x + threadIdx.x;
    if (i < KEYS) g_cnt[i] = 0;

    if (i < LL * RR * 128 * 16) {          // GAT weight split
        int q  = i & 3;
        int ks = (i >> 2) & 3;
        int n  = (i >> 4) & 127;
        int lr = i >> 11;
        const float* Wb = gW + lr * 64 * 128;    // [k][n]
        int k0 = ks * 16 + q * 2;
        unsigned h0, l0, h1, l1;
        split2(make_float2(Wb[k0 * 128 + n],       Wb[(k0 + 1) * 128 + n]), h0, l0);
        split2(make_float2(Wb[(k0 + 8) * 128 + n], Wb[(k0 + 9) * 128 + n]), h1, l1);
        g_wgf[(lr * 128 + n) * 16 + ks * 4 + q] = make_uint4(h0, h1, l0, l1);
    }
    if (i < LL * 9 * 64 * 16) {            // MLP W1 split
        int q  = i & 3;
        int ks = (i >> 2) & 3;
        int n  = (i >> 4) & 63;
        int ch = (i >> 10) % 9;
        int l  = i / (9 * 1024);
        const float* Wb = W1 + l * 576 * 64;
        int k0 = ch * 64 + ks * 16 + q * 2;
        unsigned h0, l0, h1, l1;
        split2(make_float2(Wb[k0 * 64 + n],       Wb[(k0 + 1) * 64 + n]), h0, l0);
        split2(make_float2(Wb[(k0 + 8) * 64 + n], Wb[(k0 + 9) * 64 + n]), h1, l1);
        g_w1f[((l * 9 + ch) * 64 + n) * 16 + ks * 4 + q] = make_uint4(h0, h1, l0, l1);
    }
    if (i < LL * 64 * 16) {                // MLP W2 split
        int q  = i & 3;
        int ks = (i >> 2) & 3;
        int n  = (i >> 4) & 63;
        int l  = i >> 10;
        const float* Wb = W2 + l * 64 * 64;
        int k0 = ks * 16 + q * 2;
        unsigned h0, l0, h1, l1;
        split2(make_float2(Wb[k0 * 64 + n],       Wb[(k0 + 1) * 64 + n]), h0, l0);
        split2(make_float2(Wb[(k0 + 8) * 64 + n], Wb[(k0 + 9) * 64 + n]), h1, l1);
        g_w2f[(l * 64 + n) * 16 + ks * 4 + q] = make_uint4(h0, h1, l0, l1);
    }
}

// ================= CSR build (relation-major keys) ===========================
__global__ void k_count(const int* __restrict__ ei, const float* __restrict__ ew)
{
    int e = blockIdx.x * blockDim.x + threadIdx.x;
    if (e >= EE) return;
    int s = ei[e], d = ei[EE + e];
    float w = ew[e];
    if (w == 0.f) return;
    int r0 = (w > 0.f) ? 0 : 2;
    atomicAdd(&g_cnt[r0 * NN + d], 1);
    atomicAdd(&g_cnt[(r0 + 1) * NN + s], 1);
}

__global__ void k_scan1()
{
    __shared__ int sh[SCAN_B];
    int tid = threadIdx.x;
    int i = blockIdx.x * SCAN_B + tid;
    int v = (i < KEYS) ? g_cnt[i] : 0;
    sh[tid] = v;
    __syncthreads();
    #pragma unroll
    for (int off = 1; off < SCAN_B; off <<= 1) {
        int t = (tid >= off) ? sh[tid - off] : 0;
        __syncthreads();
        sh[tid] += t;
        __syncthreads();
    }
    if (i < KEYS) g_off[i] = sh[tid] - v;
    if (tid == SCAN_B - 1) g_bsum[blockIdx.x] = sh[tid];
}

__global__ void k_scan2()
{
    __shared__ int sh[256];
    int t = threadIdx.x;
    int v = (t < SCAN_NBLK) ? g_bsum[t] : 0;
    sh[t] = v;
    __syncthreads();
    #pragma unroll
    for (int off = 1; off < 256; off <<= 1) {
        int x = (t >= off) ? sh[t - off] : 0;
        __syncthreads();
        sh[t] += x;
        __syncthreads();
    }
    if (t < SCAN_NBLK) g_bsum[t] = sh[t] - v;
}

__global__ void k_scan3()
{
    int i = blockIdx.x * blockDim.x + threadIdx.x;
    if (i >= KEYS) return;
    int o = g_off[i] + g_bsum[i >> 10];
    g_off[i] = o;
    g_cur[i] = o;
}

__global__ void k_fill(const int* __restrict__ ei, const float* __restrict__ ew)
{
    int e = blockIdx.x * blockDim.x + threadIdx.x;
    if (e >= EE) return;
    int s = ei[e], d = ei[EE + e];
    float w = ew[e];
    if (w == 0.f) return;
    int r0 = (w > 0.f) ? 0 : 2;
    int p1 = atomicAdd(&g_cur[r0 * NN + d], 1);
    g_src[p1] = s;
    int p2 = atomicAdd(&g_cur[(r0 + 1) * NN + s], 1);
    g_src[p2] = d;
}

// ================= feat GEMM (bf16-split MMA, 2-half accumulators) ===========
// Output layout: g_feat relation-major [r][n][128]; es/ed [r][n] float2.
__global__ __launch_bounds__(256, 3) void k_feat_mma(
    const float* __restrict__ hin, int l,
    const float* __restrict__ asrc, const float* __restrict__ adst)
{
    __shared__ uint4 sW[128 * 20];
    __shared__ float4 s_asad[64];      // {as[c],as[c+1],ad[c],ad[c+1]}, c=2j

    const int tid = threadIdx.x;
    const int r   = blockIdx.y;
    const int nb  = blockIdx.x * 128;

    const uint4* wg = g_wgf + (l * RR + r) * 128 * 16;
    #pragma unroll
    for (int i = tid; i < 2048; i += 256) {
        sW[(i >> 4) * 20 + (i & 15)] = wg[i];
    }
    if (tid < 64) {
        float2 a = ((const float2*)(asrc + r * 128))[tid];
        float2 d = ((const float2*)(adst + r * 128))[tid];
        s_asad[tid] = make_float4(a.x, a.y, d.x, d.y);
    }
    __syncthreads();

    const int w = tid >> 5, ln = tid & 31;
    const int g = ln >> 2, q = ln & 3;
    const int row0 = nb + w * 16 + g;
    const int ra = min(row0, NN - 1);
    const int rb = min(row0 + 8, NN - 1);
    const bool ok0 = row0 < NN, ok1 = (row0 + 8) < NN;
    float2* out2 = (float2*)g_feat;

    float esA[2] = {0.f, 0.f}, edA[2] = {0.f, 0.f};
    float esB[2] = {0.f, 0.f}, edB[2] = {0.f, 0.f};

    #pragma unroll
    for (int half = 0; half < 2; half++) {
        float c[8][4];
        #pragma unroll
        for (int t = 0; t < 8; t++) {
            c[t][0] = 0.f; c[t][1] = 0.f; c[t][2] = 0.f; c[t][3] = 0.f;
        }
        #pragma unroll
        for (int ks = 0; ks < 4; ks++) {
            int c0 = ks * 16 + q * 2;
            float2 x00 = *(const float2*)(hin + ra * 64 + c0);
            float2 x10 = *(const float2*)(hin + rb * 64 + c0);
            float2 x01 = *(const float2*)(hin + ra * 64 + c0 + 8);
            float2 x11 = *(const float2*)(hin + rb * 64 + c0 + 8);
            unsigned ahi[4], alo[4];
            split2(x00, ahi[0], alo[0]);
            split2(x10, ahi[1], alo[1]);
            split2(x01, ahi[2], alo[2]);
            split2(x11, ahi[3], alo[3]);
            #pragma unroll
            for (int tt = 0; tt < 8; tt++) {
                int t = half * 8 + tt;
                uint4 f = sW[(t * 8 + g) * 20 + ks * 4 + q];
                mma_pack(c[tt], ahi, alo, f);
            }
        }
        #pragma unroll
        for (int tt = 0; tt < 8; tt++) {
            int t = half * 8 + tt;
            int colw = t * 4 + q;
            if (ok0) out2[(r * NN + row0) * 64 + colw] = make_float2(c[tt][0], c[tt][1]);
            if (ok1) out2[(r * NN + row0 + 8) * 64 + colw] = make_float2(c[tt][2], c[tt][3]);
            float4 aa = s_asad[t * 4 + q];
            esA[half] += c[tt][0] * aa.x + c[tt][1] * aa.y;
            edA[half] += c[tt][0] * aa.z + c[tt][1] * aa.w;
            esB[half] += c[tt][2] * aa.x + c[tt][3] * aa.y;
            edB[half] += c[tt][2] * aa.z + c[tt][3] * aa.w;
        }
    }

    const unsigned FULL = 0xffffffffu;
    #pragma unroll
    for (int o = 1; o <= 2; o <<= 1) {
        esA[0] += __shfl_xor_sync(FULL, esA[0], o);
        esA[1] += __shfl_xor_sync(FULL, esA[1], o);
        esB[0] += __shfl_xor_sync(FULL, esB[0], o);
        esB[1] += __shfl_xor_sync(FULL, esB[1], o);
        edA[0] += __shfl_xor_sync(FULL, edA[0], o);
        edA[1] += __shfl_xor_sync(FULL, edA[1], o);
        edB[0] += __shfl_xor_sync(FULL, edB[0], o);
        edB[1] += __shfl_xor_sync(FULL, edB[1], o);
    }
    if (q == 0) {
        float2* es2 = (float2*)g_es;
        float2* ed2 = (float2*)g_ed;
        if (ok0) {
            es2[r * NN + row0] = make_float2(esA[0], esA[1]);
            ed2[r * NN + row0] = make_float2(edA[0], edA[1]);
        }
        if (ok1) {
            es2[r * NN + row0 + 8] = make_float2(esB[0], esB[1]);
            ed2[r * NN + row0 + 8] = make_float2(edB[0], edB[1]);
        }
    }
}

// ---------------- fused GAT: single-pass online softmax + aggregation -------
// key = r*NN + n; blocks execute relation-by-relation (50000 % 8 == 0), so the
// gather working set per phase is one 25.6MB relation slice -> L2 resident.
__global__ void k_gat(const float* __restrict__ bias)
{
    const unsigned FULL = 0xffffffffu;
    int key = blockIdx.x * 8 + (threadIdx.x >> 5);
    if (key >= KEYS) return;
    int lane = threadIdx.x & 31;
    int r = key / NN, n = key - r * NN;

    int beg = g_off[key];
    int num = g_cnt[key];

    const float2* es2 = (const float2*)g_es;
    float2 edv = ((const float2*)g_ed)[key];
    float2 esn = es2[key];
    float self0 = lrelu(esn.x + edv.x);
    float self1 = lrelu(esn.y + edv.y);

    float m0 = self0, m1 = self1;
    float den0 = 0.f, den1 = 0.f;
    float4 acc = make_float4(0.f, 0.f, 0.f, 0.f);
    const float4* feat4 = (const float4*)g_feat + (size_t)r * NN * 32;

    for (int base = 0; base < num; base += 32) {
        int cnt = min(32, num - base);
        int sj = 0;
        float ex = 0.f, ey = 0.f;
        if (lane < cnt) {
            sj = g_src[beg + base + lane];
            float2 e2 = es2[r * NN + sj];
            ex = e2.x; ey = e2.y;
        }
        for (int j = 0; j < cnt; j++) {
            int s    = __shfl_sync(FULL, sj, j);
            float jx = __shfl_sync(FULL, ex, j);
            float jy = __shfl_sync(FULL, ey, j);
            float e0 = lrelu(jx + edv.x);
            float e1 = lrelu(jy + edv.y);
            float4 f = feat4[s * 32 + lane];
            if (e0 > m0 || e1 > m1) {           // warp-uniform rescale path
                float nm0 = fmaxf(m0, e0), nm1 = fmaxf(m1, e1);
                float c0 = __expf(m0 - nm0), c1 = __expf(m1 - nm1);
                float p0 = __expf(e0 - nm0), p1 = __expf(e1 - nm1);
                den0 = den0 * c0 + p0;
                den1 = den1 * c1 + p1;
                m0 = nm0; m1 = nm1;
                float cl = (lane < 16) ? c0 : c1;
                float pl = (lane < 16) ? p0 : p1;
                acc.x = acc.x * cl + pl * f.x;
                acc.y = acc.y * cl + pl * f.y;
                acc.z = acc.z * cl + pl * f.z;
                acc.w = acc.w * cl + pl * f.w;
            } else {
                float p0 = __expf(e0 - m0);
                float p1 = __expf(e1 - m1);
                den0 += p0; den1 += p1;
                float pl = (lane < 16) ? p0 : p1;
                acc.x += pl * f.x; acc.y += pl * f.y;
                acc.z += pl * f.z; acc.w += pl * f.w;
            }
        }
    }
    // self loop (self <= m always)
    {
        float p0 = __expf(self0 - m0);
        float p1 = __expf(self1 - m1);
        den0 += p0; den1 += p1;
        float pl = (lane < 16) ? p0 : p1;
        float4 f = feat4[n * 32 + lane];
        acc.x += pl * f.x; acc.y += pl * f.y;
        acc.z += pl * f.z; acc.w += pl * f.w;
    }

    float inv = 1.f / ((lane < 16) ? den0 : den1);
    float4 b = ((const float4*)bias)[r * 32 + lane];
    ((float4*)g_agg)[n * 128 + r * 32 + lane] =
        make_float4(acc.x * inv + b.x, acc.y * inv + b.y,
                    acc.z * inv + b.z, acc.w * inv + b.w);
}

// ================= MLP via bf16-split MMA + fused residual/LN ================
__global__ __launch_bounds__(256, 3) void k_mlp_mma(
    const float* __restrict__ hin, int l,
    const float* __restrict__ b1, const float* __restrict__ b2,
    const float* __restrict__ lng, const float* __restrict__ lnb,
    float* __restrict__ hout)
{
    __shared__ uint4 sW[64 * 20];
    __shared__ float2 s_b1[32];        // {b1[c], b1[c+1]}
    __shared__ float4 s_bg[32];        // {b2[c], b2[c+1], lng[c], lng[c+1]}
    __shared__ float2 s_lb[32];        // {lnb[c], lnb[c+1]}

    const int tid = threadIdx.x;
    const int w = tid >> 5, ln = tid & 31;
    const int g = ln >> 2, q = ln & 3;
    const int nb = blockIdx.x * 128;
    const int row0 = nb + w * 16 + g;
    const int ra = min(row0, NN - 1);
    const int rb = min(row0 + 8, NN - 1);

    if (tid < 32) {
        s_b1[tid] = ((const float2*)b1)[tid];
        float2 bb = ((const float2*)b2)[tid];
        float2 gg = ((const float2*)lng)[tid];
        s_bg[tid] = make_float4(bb.x, bb.y, gg.x, gg.y);
        s_lb[tid] = ((const float2*)lnb)[tid];
    }

    float c1[8][4];
    #pragma unroll
    for (int t = 0; t < 8; t++) {
        c1[t][0] = 0.f; c1[t][1] = 0.f; c1[t][2] = 0.f; c1[t][3] = 0.f;
    }

    const uint4* w1f = g_w1f + l * 9 * 1024;

    for (int ch = 0; ch < 9; ch++) {
        __syncthreads();
        #pragma unroll
        for (int i = tid; i < 1024; i += 256) {
            sW[(i >> 4) * 20 + (i & 15)] = w1f[ch * 1024 + i];
        }
        __syncthreads();

        #pragma unroll
        for (int ks = 0; ks < 4; ks++) {
            float2 x00, x10, x01, x11;
            if (ch == 0) {
                int c0 = ks * 16 + q * 2;
                x00 = *(const float2*)(hin + ra * 64 + c0);
                x10 = *(const float2*)(hin + rb * 64 + c0);
                x01 = *(const float2*)(hin + ra * 64 + c0 + 8);
                x11 = *(const float2*)(hin + rb * 64 + c0 + 8);
            } else {
                int c0 = (ch - 1) * 64 + ks * 16 + q * 2;
                x00 = *(const float2*)(g_agg + ra * 512 + c0);
                x10 = *(const float2*)(g_agg + rb * 512 + c0);
                x01 = *(const float2*)(g_agg + ra * 512 + c0 + 8);
                x11 = *(const float2*)(g_agg + rb * 512 + c0 + 8);
            }
            unsigned ahi[4], alo[4];
            split2(x00, ahi[0], alo[0]);
            split2(x10, ahi[1], alo[1]);
            split2(x01, ahi[2], alo[2]);
            split2(x11, ahi[3], alo[3]);

            #pragma unroll
            for (int t = 0; t < 8; t++) {
                uint4 f = sW[(t * 8 + g) * 20 + ks * 4 + q];
                mma_pack(c1[t], ahi, alo, f);
            }
        }
    }

    // ---- tanh + bias -> A fragments for GEMM2 ----
    unsigned ahi2[4][4], alo2[4][4];
    #pragma unroll
    for (int t = 0; t < 8; t++) {
        float2 bj = s_b1[t * 4 + q];
        float z0 = tanhf(c1[t][0] + bj.x);
        float z1 = tanhf(c1[t][1] + bj.y);
        float z2 = tanhf(c1[t][2] + bj.x);
        float z3 = tanhf(c1[t][3] + bj.y);
        int kt = t >> 1;
        int o = (t & 1) ? 2 : 0;
        split2(make_float2(z0, z1), ahi2[kt][o + 0], alo2[kt][o + 0]);
        split2(make_float2(z2, z3), ahi2[kt][o + 1], alo2[kt][o + 1]);
    }

    __syncthreads();
    #pragma unroll
    for (int i = tid; i < 1024; i += 256) {
        sW[(i >> 4) * 20 + (i & 15)] = g_w2f[l * 1024 + i];
    }
    __syncthreads();

    float c2[8][4];
    #pragma unroll
    for (int t = 0; t < 8; t++) {
        c2[t][0] = 0.f; c2[t][1] = 0.f; c2[t][2] = 0.f; c2[t][3] = 0.f;
    }
    #pragma unroll
    for (int kt = 0; kt < 4; kt++) {
        #pragma unroll
        for (int t = 0; t < 8; t++) {
            uint4 f = sW[(t * 8 + g) * 20 + kt * 4 + q];
            mma_pack(c2[t], ahi2[kt], alo2[kt], f);
        }
    }

    // ---- +b2 +residual (in place), LayerNorm sums ----
    float sA = 0.f, qA = 0.f, sB = 0.f, qB = 0.f;
    #pragma unroll
    for (int t = 0; t < 8; t++) {
        int col0 = t * 8 + q * 2;
        float4 bg = s_bg[t * 4 + q];
        float2 r0 = *(const float2*)(hin + ra * 64 + col0);
        float2 r1 = *(const float2*)(hin + rb * 64 + col0);
        c2[t][0] += bg.x + r0.x;
        c2[t][1] += bg.y + r0.y;
        c2[t][2] += bg.x + r1.x;
        c2[t][3] += bg.y + r1.y;
        sA += c2[t][0] + c2[t][1];
        qA += c2[t][0] * c2[t][0] + c2[t][1] * c2[t][1];
        sB += c2[t][2] + c2[t][3];
        qB += c2[t][2] * c2[t][2] + c2[t][3] * c2[t][3];
    }
    const unsigned FULL = 0xffffffffu;
    #pragma unroll
    for (int o = 1; o <= 2; o <<= 1) {
        sA += __shfl_xor_sync(FULL, sA, o);
        qA += __shfl_xor_sync(FULL, qA, o);
        sB += __shfl_xor_sync(FULL, sB, o);
        qB += __shfl_xor_sync(FULL, qB, o);
    }
    float muA = sA * (1.f / 64.f);
    float rsA = rsqrtf(qA * (1.f / 64.f) - muA * muA + LN_EPS);
    float muB = sB * (1.f / 64.f);
    float rsB = rsqrtf(qB * (1.f / 64.f) - muB * muB + LN_EPS);

    const bool ok0 = row0 < NN, ok1 = (row0 + 8) < NN;
    #pragma unroll
    for (int t = 0; t < 8; t++) {
        int col0 = t * 8 + q * 2;
        float4 bg = s_bg[t * 4 + q];
        float2 ob = s_lb[t * 4 + q];
        if (ok0)
            *(float2*)(hout + row0 * 64 + col0) =
                make_float2((c2[t][0] - muA) * rsA * bg.z + ob.x,
                            (c2[t][1] - muA) * rsA * bg.w + ob.y);
        if (ok1)
            *(float2*)(hout + (row0 + 8) * 64 + col0) =
                make_float2((c2[t][2] - muB) * rsB * bg.z + ob.x,
                            (c2[t][3] - muB) * rsB * bg.w + ob.y);
    }
}

// ---------------- launch -----------------------------------------------------
extern "C" void kernel_launch(void* const* d_in, const int* in_sizes, int n_in,
                              void* d_out, int out_size)
{
    const float* x   = (const float*)d_in[0];
    const int*   ei  = (const int*)  d_in[1];
    const float* ew  = (const float*)d_in[2];
    const float* gW  = (const float*)d_in[3];
    const float* gas = (const float*)d_in[4];
    const float* gad = (const float*)d_in[5];
    const float* gb  = (const float*)d_in[6];
    const float* W1  = (const float*)d_in[7];
    const float* b1  = (const float*)d_in[8];
    const float* W2  = (const float*)d_in[9];
    const float* b2  = (const float*)d_in[10];
    const float* lng = (const float*)d_in[11];
    const float* lnb = (const float*)d_in[12];
    float* out = (float*)d_out;

    float* hptr = nullptr;
    cudaGetSymbolAddress((void**)&hptr, g_h);

    const int EB  = (EE + 255) / 256;
    const int KB  = (KEYS + 255) / 256;
    const int FT  = (NN + 127) / 128;       // 391 tiles of 128 nodes

    // k_feat_mma at launch index 3 (ncu capture slot)
    k_init <<<KB, 256>>>(gW, W1, W2);
    k_count<<<EB, 256>>>(ei, ew);
    k_scan1<<<SCAN_NBLK, SCAN_B>>>();
    k_feat_mma<<<dim3(FT, RR), 256>>>(x, 0, gas, gad);          // layer 0
    k_scan2<<<1, 256>>>();
    k_scan3<<<KB, 256>>>();
    k_fill <<<EB, 256>>>(ei, ew);

    // layer 0 tail
    k_gat<<<KEYS / 8, 256>>>(gb);
    k_mlp_mma<<<FT, 256>>>(x, 0, b1, b2, lng, lnb, hptr);

    // layer 1
    k_feat_mma<<<dim3(FT, RR), 256>>>(hptr, 1,
                                      gas + RR * HH * CC, gad + RR * HH * CC);
    k_gat<<<KEYS / 8, 256>>>(gb + RR * HCC);
    k_mlp_mma<<<FT, 256>>>(hptr, 1, b1 + 64, b2 + 64,
                           lng + 64, lnb + 64, out);
}